// round 5
// baseline (speedup 1.0000x reference)
#include <cuda_runtime.h>
#include <cstdint>

#define LSEQ 512
#define UDIM 512
#define BDIM 4
#define HDIM 8
#define DDIM 64
#define HBDIM 32

typedef unsigned long long ull;

// ---------------- scratch (device globals, no allocation) ----------------
__device__ float g_Q[BDIM * LSEQ * UDIM];
__device__ float g_K[BDIM * LSEQ * UDIM];
__device__ float g_V[BDIM * LSEQ * UDIM];
__device__ float g_Wt[3 * UDIM * UDIM];        // W transposed: [z][n][k]
__device__ float g_qm[BDIM * LSEQ];
__device__ float g_Qn[HDIM * BDIM * LSEQ];     // ||Q_head||^2 per (h, b, row)
__device__ float g_Kn[HDIM * BDIM * LSEQ];     // ||K_head||^2 per (h, b, row)

// ---------------- packed f32x2 + approx helpers ----------------
__device__ __forceinline__ void fma2(ull& d, ull a, ull b) {
    asm("fma.rn.f32x2 %0, %1, %2, %0;" : "+l"(d) : "l"(a), "l"(b));
}
__device__ __forceinline__ ull pk2(float x, float y) {
    ull r; asm("mov.b64 %0, {%1, %2};" : "=l"(r) : "f"(x), "f"(y)); return r;
}
__device__ __forceinline__ float2 upk(ull v) {
    float2 f; asm("mov.b64 {%0, %1}, %2;" : "=f"(f.x), "=f"(f.y) : "l"(v)); return f;
}
__device__ __forceinline__ float hsum(ull v) { float2 f = upk(v); return f.x + f.y; }
__device__ __forceinline__ float sqrt_ap(float x) {
    float r; asm("sqrt.approx.f32 %0, %1;" : "=f"(r) : "f"(x)); return r;
}
__device__ __forceinline__ float ex2_ap(float x) {
    float r; asm("ex2.approx.f32 %0, %1;" : "=f"(r) : "f"(x)); return r;
}

// ---------------- cp.async helpers ----------------
__device__ __forceinline__ void cpa16(void* sdst, const void* gsrc) {
    uint32_t s = (uint32_t)__cvta_generic_to_shared(sdst);
    asm volatile("cp.async.cg.shared.global [%0], [%1], 16;" :: "r"(s), "l"(gsrc));
}
#define CPA_COMMIT() asm volatile("cp.async.commit_group;")
#define CPA_WAIT(n)  asm volatile("cp.async.wait_group %0;" :: "n"(n))

// ---------------- kernel 0: transpose W (3 MB, once) ----------------
__global__ void transpose_w_kernel(const float* __restrict__ Wq,
                                   const float* __restrict__ Wk,
                                   const float* __restrict__ Wv) {
    __shared__ float t[32][33];
    const float* W = (blockIdx.z == 0) ? Wq : (blockIdx.z == 1) ? Wk : Wv;
    float* D = g_Wt + (size_t)blockIdx.z * UDIM * UDIM;
    int k0 = blockIdx.x * 32;
    int n0 = blockIdx.y * 32;
    int tx = threadIdx.x & 31, ty = threadIdx.x >> 5;
    #pragma unroll
    for (int i = 0; i < 4; i++) {
        int r = ty + i * 8;
        t[r][tx] = W[(size_t)(k0 + r) * UDIM + n0 + tx];
    }
    __syncthreads();
    #pragma unroll
    for (int i = 0; i < 4; i++) {
        int r = ty + i * 8;
        D[(size_t)(n0 + r) * UDIM + k0 + tx] = t[tx][r];
    }
}

// ---------------- kernel 1: fused GEMM + bias + relu + head-norms ----------
// C[2048x512] = relu(X @ W + b). BM=64, BN=64, BK=32, 256 thr, 4m x 4n/thread.
// BN=64 == one head's d-slice -> exact row norms via 16-lane shfl in epilogue.
#define GBM 64
#define GBN 64
#define GBK 32
#define GST 36
#define GXSZ (GBM * GST)
#define GWSZ (GBN * GST)

__global__ __launch_bounds__(256, 2)
void qkv_gemm_kernel(const float* __restrict__ q_in,
                     const float* __restrict__ k_in,
                     const float* __restrict__ v_in,
                     const float* __restrict__ bq,
                     const float* __restrict__ bk,
                     const float* __restrict__ bv) {
    __shared__ float Xs[2][GXSZ];
    __shared__ float Ws[2][GWSZ];

    const float* X; const float* bias; float* dst;
    if (blockIdx.z == 0)      { X = q_in; bias = bq; dst = g_Q; }
    else if (blockIdx.z == 1) { X = k_in; bias = bk; dst = g_K; }
    else                      { X = v_in; bias = bv; dst = g_V; }
    const float* Wt = g_Wt + (size_t)blockIdx.z * UDIM * UDIM;

    const int tid = threadIdx.x;
    const int m0 = blockIdx.x * GBM;
    const int n0 = blockIdx.y * GBN;
    const int ty = tid >> 4;
    const int tx = tid & 15;

    auto issue = [&](int t, int buf) {
        #pragma unroll
        for (int i = 0; i < 2; i++) {
            int lin = tid + i * 256;
            int r = lin >> 3, c = lin & 7;
            cpa16(&Xs[buf][r * GST + c * 4], X + (size_t)(m0 + r) * UDIM + t * GBK + c * 4);
        }
        #pragma unroll
        for (int i = 0; i < 2; i++) {
            int lin = tid + i * 256;
            int r = lin >> 3, c = lin & 7;
            cpa16(&Ws[buf][r * GST + c * 4], Wt + (size_t)(n0 + r) * UDIM + t * GBK + c * 4);
        }
        CPA_COMMIT();
    };

    ull acc[4][4] = {};
    issue(0, 0);

    for (int t = 0; t < 16; t++) {
        if (t < 15) { issue(t + 1, (t + 1) & 1); CPA_WAIT(1); }
        else        { CPA_WAIT(0); }
        __syncthreads();

        const float* xb = &Xs[t & 1][ty * 4 * GST];
        const float* wb = &Ws[t & 1][0];
        #pragma unroll
        for (int k4 = 0; k4 < 8; k4++) {
            ulonglong2 w[4];
            #pragma unroll
            for (int j = 0; j < 4; j++)
                w[j] = *(const ulonglong2*)(wb + (tx + 16 * j) * GST + k4 * 4);
            #pragma unroll
            for (int i = 0; i < 4; i++) {
                ulonglong2 a = *(const ulonglong2*)(xb + i * GST + k4 * 4);
                #pragma unroll
                for (int j = 0; j < 4; j++) {
                    fma2(acc[i][j], a.x, w[j].x);
                    fma2(acc[i][j], a.y, w[j].y);
                }
            }
        }
        __syncthreads();
    }

    float bv4[4];
    #pragma unroll
    for (int j = 0; j < 4; j++) bv4[j] = bias[n0 + tx + 16 * j];

    float ss[4] = {0.f, 0.f, 0.f, 0.f};
    #pragma unroll
    for (int i = 0; i < 4; i++) {
        size_t mrow = (size_t)(m0 + ty * 4 + i) * UDIM;
        #pragma unroll
        for (int j = 0; j < 4; j++) {
            float v = hsum(acc[i][j]) + bv4[j];
            v = v > 0.f ? v : 0.f;
            ss[i] += v * v;
            dst[mrow + n0 + tx + 16 * j] = v;
        }
    }

    // head-norm epilogue (Q and K problems only): reduce ss over the 16 tx lanes
    if (blockIdx.z < 2) {
        float* ndst = (blockIdx.z == 0) ? g_Qn : g_Kn;
        #pragma unroll
        for (int i = 0; i < 4; i++) {
            #pragma unroll
            for (int o = 1; o < 16; o <<= 1)
                ss[i] += __shfl_xor_sync(0xffffffffu, ss[i], o);
        }
        if (tx == 0) {
            int base = (n0 >> 6) * (BDIM * LSEQ) + m0 + ty * 4;
            #pragma unroll
            for (int i = 0; i < 4; i++) ndst[base + i] = ss[i];
        }
    }
}

// ---------------- kernel 2: query mask ----------------
__global__ void qm_kernel(const float* __restrict__ q_in) {
    int warp = (blockIdx.x * blockDim.x + threadIdx.x) >> 5;
    int lane = threadIdx.x & 31;
    if (warp >= BDIM * LSEQ) return;
    float s = 0.f;
    for (int e = lane; e < UDIM; e += 32) s += q_in[(size_t)warp * UDIM + e];
    #pragma unroll
    for (int o = 16; o; o >>= 1) s += __shfl_xor_sync(0xffffffffu, s, o);
    if (lane == 0) g_qm[warp] = (s != 0.f) ? 1.f : 0.f;
}

// ---------------- kernel 3: fused euclidean attention ----------------
// Block = 64 q-rows x one hb, 256 thr, 2 blocks/SM (reg diet: norms hoisted,
// split-j S-compute). Grid 256 <= 296 resident -> one wave. 8 k-tiles of 64,
// 3-buffer cp.async rotation, fixed-max softmax (scores <= 0).
#define A_QST 64
#define A_KST 68
#define A_SST 68
#define A_KVSZ (64 * A_KST)
#define AOFF_Q  0
#define AOFF_KV (64 * A_QST)                      // 4096
#define AOFF_SS (AOFF_KV + 3 * A_KVSZ)            // 4096 + 13056 = 17152
#define AOFF_KN (AOFF_SS + 64 * A_SST)            // 17152 + 4352 = 21504
#define AOFF_QQ (AOFF_KN + 2 * 64)                // 21632
#define ATTN_SMEM_FLOATS (AOFF_QQ + 64)           // 21696
#define ATTN_SMEM_BYTES (ATTN_SMEM_FLOATS * 4)    // 86784

__global__ __launch_bounds__(256, 2)
void attn_kernel(float* __restrict__ out, float* __restrict__ score_out) {
    extern __shared__ float smf[];
    float* Qs = smf + AOFF_Q;
    float* KV = smf + AOFF_KV;
    float* Ss = smf + AOFF_SS;
    float* kn_s = smf + AOFF_KN;     // [2][64] double-buffered K norms
    float* qq_s = smf + AOFF_QQ;

    const int tid = threadIdx.x;
    const int ty = tid >> 4;      // 0..15 -> 4 q-rows each (broadcast reads)
    const int tx = tid & 15;      // k-cols {tx + 16j} / d-cols tx*4..+3
    const int q0 = blockIdx.x * 64;
    const int hb = blockIdx.y;
    const int h = hb >> 2;        // hb = h*BDIM + b
    const int b = hb & 3;

    const float* Qg = g_Q + ((size_t)(b * LSEQ + q0)) * UDIM + h * DDIM;
    const float* Kg = g_K + ((size_t)(b * LSEQ)) * UDIM + h * DDIM;
    const float* Vg = g_V + ((size_t)(b * LSEQ)) * UDIM + h * DDIM;
    const float* Qn = g_Qn + (size_t)h * (BDIM * LSEQ) + b * LSEQ + q0;
    const float* Kn = g_Kn + (size_t)h * (BDIM * LSEQ) + b * LSEQ;

    auto load_v = [&](const float* src, float* dst) {
        #pragma unroll
        for (int i = 0; i < 4; i++) {
            int lin = tid + i * 256;
            int r = lin >> 4, c = lin & 15;
            cpa16(dst + r * A_KST + c * 4, src + (size_t)r * UDIM + c * 4);
        }
    };
    auto load_k = [&](int t, float* dst) {
        load_v(Kg + (size_t)t * 64 * UDIM, dst);
        if (tid < 16) cpa16(kn_s + (t & 1) * 64 + tid * 4, Kn + t * 64 + tid * 4);
    };

    // group 0: Q + qq + K0 + kn0
    #pragma unroll
    for (int i = 0; i < 4; i++) {
        int lin = tid + i * 256;
        int r = lin >> 4, c = lin & 15;
        cpa16(Qs + r * A_QST + c * 4, Qg + (size_t)r * UDIM + c * 4);
    }
    if (tid < 16) cpa16(qq_s + tid * 4, Qn + tid * 4);
    load_k(0, KV + 0 * A_KVSZ);
    CPA_COMMIT();                                   // idx 0
    load_v(Vg, KV + 1 * A_KVSZ);
    CPA_COMMIT();                                   // idx 1: V0
    load_k(1, KV + 2 * A_KVSZ);
    CPA_COMMIT();                                   // idx 2: K1

    float qm_r[4], l_acc[4];
    #pragma unroll
    for (int i = 0; i < 4; i++) {
        qm_r[i] = g_qm[b * LSEQ + q0 + ty * 4 + i];
        l_acc[i] = 0.f;
    }

    CPA_WAIT(2);
    __syncthreads();

    float qq_r[4];
    #pragma unroll
    for (int i = 0; i < 4; i++) qq_r[i] = qq_s[ty * 4 + i];

    ull oacc[4][2] = {};
    const float LOG2E = 1.4426950408889634f;

    for (int t = 0; t < 8; t++) {
        float* Kb = KV + ((2 * t) % 3) * A_KVSZ;
        float* Vb = KV + ((2 * t + 1) % 3) * A_KVSZ;

        if (t >= 1 && t <= 6) load_k(t + 1, KV + ((2 * t + 2) % 3) * A_KVSZ);
        CPA_COMMIT();
        CPA_WAIT(2);                                // K_t (+kn_t) ready
        __syncthreads();

        // ---- S compute: split-j (2 k-cols live at a time) ----
        #pragma unroll
        for (int jh = 0; jh < 2; jh++) {
            ull dot[4][2] = {};
            #pragma unroll
            for (int d4 = 0; d4 < 16; d4++) {
                ulonglong2 kv0 = *(const ulonglong2*)(Kb + (tx + 32 * jh) * A_KST + d4 * 4);
                ulonglong2 kv1 = *(const ulonglong2*)(Kb + (tx + 32 * jh + 16) * A_KST + d4 * 4);
                #pragma unroll
                for (int i = 0; i < 4; i++) {
                    ulonglong2 a = *(const ulonglong2*)(Qs + (ty * 4 + i) * A_QST + d4 * 4);
                    fma2(dot[i][0], a.x, kv0.x); fma2(dot[i][0], a.y, kv0.y);
                    fma2(dot[i][1], a.x, kv1.x); fma2(dot[i][1], a.y, kv1.y);
                }
            }
            float kk0 = kn_s[(t & 1) * 64 + tx + 32 * jh];
            float kk1 = kn_s[(t & 1) * 64 + tx + 32 * jh + 16];
            #pragma unroll
            for (int i = 0; i < 4; i++) {
                int r = ty * 4 + i;
                size_t srow = ((size_t)(hb * LSEQ + q0 + r)) * LSEQ + t * 64;
                float d20 = fmaxf(qq_r[i] + kk0 - 2.f * hsum(dot[i][0]), 1e-12f);
                float d21 = fmaxf(qq_r[i] + kk1 - 2.f * hsum(dot[i][1]), 1e-12f);
                float s0 = -sqrt_ap(d20) * 0.125f;
                float s1 = -sqrt_ap(d21) * 0.125f;
                score_out[srow + tx + 32 * jh]      = s0 * qm_r[i];
                score_out[srow + tx + 32 * jh + 16] = s1 * qm_r[i];
                float p0 = ex2_ap(s0 * LOG2E);
                float p1 = ex2_ap(s1 * LOG2E);
                Ss[r * A_SST + tx + 32 * jh]      = p0;
                Ss[r * A_SST + tx + 32 * jh + 16] = p1;
                l_acc[i] += p0 + p1;
            }
        }
        __syncthreads();     // Ss ready; Kb fully consumed

        if (t < 7) load_v(Vg + (size_t)(t + 1) * 64 * UDIM, KV + ((2 * t) % 3) * A_KVSZ);
        CPA_COMMIT();
        CPA_WAIT(2);                                // V_t ready
        __syncthreads();

        // ---- PV accumulate: O += P * V ----
        #pragma unroll
        for (int k4 = 0; k4 < 16; k4++) {
            float4 p4[4];
            #pragma unroll
            for (int i = 0; i < 4; i++)
                p4[i] = *(const float4*)(Ss + (ty * 4 + i) * A_SST + k4 * 4);
            #pragma unroll
            for (int kk_ = 0; kk_ < 4; kk_++) {
                ulonglong2 v = *(const ulonglong2*)(Vb + (k4 * 4 + kk_) * A_KST + tx * 4);
                #pragma unroll
                for (int i = 0; i < 4; i++) {
                    float pe = ((const float*)&p4[i])[kk_];
                    ull p2 = pk2(pe, pe);
                    fma2(oacc[i][0], p2, v.x);
                    fma2(oacc[i][1], p2, v.y);
                }
            }
        }
        __syncthreads();     // V_t consumed before next K prefetch overwrite
    }

    // l reduction across the 16 tx lanes sharing each q-row
    #pragma unroll
    for (int i = 0; i < 4; i++) {
        #pragma unroll
        for (int o = 1; o < 16; o <<= 1)
            l_acc[i] += __shfl_xor_sync(0xffffffffu, l_acc[i], o);
    }

    // epilogue: out = (O / l) * qm, merged-head layout
    #pragma unroll
    for (int i = 0; i < 4; i++) {
        int r = ty * 4 + i;
        float scale = qm_r[i] / l_acc[i];
        float2 f0 = upk(oacc[i][0]);
        float2 f1 = upk(oacc[i][1]);
        float4 o;
        o.x = f0.x * scale; o.y = f0.y * scale;
        o.z = f1.x * scale; o.w = f1.y * scale;
        *(float4*)(out + ((size_t)(b * LSEQ + q0 + r)) * UDIM + h * DDIM + tx * 4) = o;
    }
}

// ---------------- launcher ----------------
extern "C" void kernel_launch(void* const* d_in, const int* in_sizes, int n_in,
                              void* d_out, int out_size) {
    (void)in_sizes; (void)n_in; (void)out_size;
    const float* queries = (const float*)d_in[0];
    const float* keys    = (const float*)d_in[1];
    const float* values  = (const float*)d_in[2];
    const float* Wq = (const float*)d_in[3];
    const float* bq = (const float*)d_in[4];
    const float* Wk = (const float*)d_in[5];
    const float* bk = (const float*)d_in[6];
    const float* Wv = (const float*)d_in[7];
    const float* bv = (const float*)d_in[8];

    float* out_ptr   = (float*)d_out;
    float* score_ptr = out_ptr + (size_t)BDIM * LSEQ * UDIM;

    cudaFuncSetAttribute(attn_kernel, cudaFuncAttributeMaxDynamicSharedMemorySize,
                         ATTN_SMEM_BYTES);

    dim3 tgrid(UDIM / 32, UDIM / 32, 3);
    transpose_w_kernel<<<tgrid, 256>>>(Wq, Wk, Wv);

    dim3 ggrid(BDIM * LSEQ / GBM, UDIM / GBN, 3);
    qkv_gemm_kernel<<<ggrid, 256>>>(queries, keys, values, bq, bk, bv);

    qm_kernel<<<(BDIM * LSEQ * 32) / 256, 256>>>(queries);

    dim3 agrid(LSEQ / 64, HBDIM);
    attn_kernel<<<agrid, 256, ATTN_SMEM_BYTES>>>(out_ptr, score_ptr);
}

// round 6
// speedup vs baseline: 1.3449x; 1.3449x over previous
#include <cuda_runtime.h>
#include <cstdint>

#define LSEQ 512
#define UDIM 512
#define BDIM 4
#define HDIM 8
#define DDIM 64
#define HBDIM 32

typedef unsigned long long ull;

// ---------------- scratch (device globals, no allocation) ----------------
__device__ float g_Q[BDIM * LSEQ * UDIM];
__device__ float g_K[BDIM * LSEQ * UDIM];
__device__ float g_V[BDIM * LSEQ * UDIM];
__device__ float g_Wt[3 * UDIM * UDIM];        // W transposed: [z][n][k]
__device__ float g_qm[BDIM * LSEQ];
__device__ float g_Qn[HDIM * BDIM * LSEQ];     // ||Q_head||^2 per (h, b*L+row)
__device__ float g_Kn[HDIM * BDIM * LSEQ];

// ---------------- packed f32x2 helpers ----------------
__device__ __forceinline__ void fma2(ull& d, ull a, ull b) {
    asm("fma.rn.f32x2 %0, %1, %2, %0;" : "+l"(d) : "l"(a), "l"(b));
}
__device__ __forceinline__ ull pk2(float x, float y) {
    ull r; asm("mov.b64 %0, {%1, %2};" : "=l"(r) : "f"(x), "f"(y)); return r;
}
__device__ __forceinline__ float2 upk(ull v) {
    float2 f; asm("mov.b64 {%0, %1}, %2;" : "=f"(f.x), "=f"(f.y) : "l"(v)); return f;
}
__device__ __forceinline__ float hsum(ull v) { float2 f = upk(v); return f.x + f.y; }

// ---- MUFU-free sqrt: rsqrt bit-hack + 2 Newton steps (rel err ~4e-6) ----
__device__ __forceinline__ float sqrt_nm(float x) {
    float r = __int_as_float(0x5f3759df - (__float_as_int(x) >> 1));
    r = r * (1.5f - 0.5f * x * r * r);
    r = r * (1.5f - 0.5f * x * r * r);
    return x * r;
}

// ---- MUFU-free exp2 for y <= 0 (rel err ~2.4e-6) ----
__device__ __forceinline__ float exp2_poly(float y) {
    y = fmaxf(y, -120.f);
    float fn = y + 12582912.f;              // RN-add puts round(y) in mantissa
    int ib = __float_as_int(fn);            // = 0x4B400000 + n
    float n = fn - 12582912.f;
    float f = y - n;                        // f in [-0.5, 0.5]
    float scale = __int_as_float((ib - 0x4B400000 + 127) << 23);  // 2^n
    float p = 0.0013333558f;
    p = fmaf(p, f, 0.0096181291f);
    p = fmaf(p, f, 0.0555041087f);
    p = fmaf(p, f, 0.2402265069f);
    p = fmaf(p, f, 0.6931471806f);
    p = fmaf(p, f, 1.0f);
    return scale * p;
}

// ---------------- cp.async helpers ----------------
__device__ __forceinline__ void cpa16(void* sdst, const void* gsrc) {
    uint32_t s = (uint32_t)__cvta_generic_to_shared(sdst);
    asm volatile("cp.async.cg.shared.global [%0], [%1], 16;" :: "r"(s), "l"(gsrc));
}
#define CPA_COMMIT() asm volatile("cp.async.commit_group;")
#define CPA_WAIT(n)  asm volatile("cp.async.wait_group %0;" :: "n"(n))

// ---------------- kernel 0: transpose W (3 MB, once) ----------------
__global__ void transpose_w_kernel(const float* __restrict__ Wq,
                                   const float* __restrict__ Wk,
                                   const float* __restrict__ Wv) {
    __shared__ float t[32][33];
    const float* W = (blockIdx.z == 0) ? Wq : (blockIdx.z == 1) ? Wk : Wv;
    float* D = g_Wt + (size_t)blockIdx.z * UDIM * UDIM;
    int k0 = blockIdx.x * 32;
    int n0 = blockIdx.y * 32;
    int tx = threadIdx.x & 31, ty = threadIdx.x >> 5;
    #pragma unroll
    for (int i = 0; i < 4; i++) {
        int r = ty + i * 8;
        t[r][tx] = W[(size_t)(k0 + r) * UDIM + n0 + tx];
    }
    __syncthreads();
    #pragma unroll
    for (int i = 0; i < 4; i++) {
        int r = ty + i * 8;
        D[(size_t)(n0 + r) * UDIM + k0 + tx] = t[tx][r];
    }
}

// ---------------- kernel 1: fused GEMM + bias + relu + head-norms ----------
// BM=128, BN=64, BK=32, 256 thr, 8m x 4n/thread (1.5 B/MAC -> LDS not binding)
#define GBM 128
#define GBN 64
#define GBK 32
#define GST 36
#define GXSZ (GBM * GST)
#define GWSZ (GBN * GST)
#define GEMM_SMEM_BYTES ((2 * GXSZ + 2 * GWSZ) * 4)   // 55296

__global__ __launch_bounds__(256, 1)
void qkv_gemm_kernel(const float* __restrict__ q_in,
                     const float* __restrict__ k_in,
                     const float* __restrict__ v_in,
                     const float* __restrict__ bq,
                     const float* __restrict__ bk,
                     const float* __restrict__ bv) {
    extern __shared__ float gsm[];
    float* Xs = gsm;                 // [2][GXSZ]
    float* Ws = gsm + 2 * GXSZ;      // [2][GWSZ]

    const float* X; const float* bias; float* dst;
    if (blockIdx.z == 0)      { X = q_in; bias = bq; dst = g_Q; }
    else if (blockIdx.z == 1) { X = k_in; bias = bk; dst = g_K; }
    else                      { X = v_in; bias = bv; dst = g_V; }
    const float* Wt = g_Wt + (size_t)blockIdx.z * UDIM * UDIM;

    const int tid = threadIdx.x;
    const int m0 = blockIdx.x * GBM;
    const int n0 = blockIdx.y * GBN;
    const int ty = tid >> 4;      // 0..15 -> 8 m-rows each (broadcast reads)
    const int tx = tid & 15;      // n cols {tx + 16j} (phase rows consecutive)

    auto issue = [&](int t, int buf) {
        #pragma unroll
        for (int i = 0; i < 4; i++) {               // X: 128x32 -> 4/thread
            int lin = tid + i * 256;
            int r = lin >> 3, c = lin & 7;
            cpa16(&Xs[buf * GXSZ + r * GST + c * 4],
                  X + (size_t)(m0 + r) * UDIM + t * GBK + c * 4);
        }
        #pragma unroll
        for (int i = 0; i < 2; i++) {               // W: 64x32 -> 2/thread
            int lin = tid + i * 256;
            int r = lin >> 3, c = lin & 7;
            cpa16(&Ws[buf * GWSZ + r * GST + c * 4],
                  Wt + (size_t)(n0 + r) * UDIM + t * GBK + c * 4);
        }
        CPA_COMMIT();
    };

    ull acc[8][4] = {};
    issue(0, 0);

    for (int t = 0; t < 16; t++) {
        if (t < 15) { issue(t + 1, (t + 1) & 1); CPA_WAIT(1); }
        else        { CPA_WAIT(0); }
        __syncthreads();

        const float* xb = &Xs[(t & 1) * GXSZ + ty * 8 * GST];
        const float* wb = &Ws[(t & 1) * GWSZ];
        #pragma unroll
        for (int k4 = 0; k4 < 8; k4++) {
            ulonglong2 w[4];
            #pragma unroll
            for (int j = 0; j < 4; j++)
                w[j] = *(const ulonglong2*)(wb + (tx + 16 * j) * GST + k4 * 4);
            #pragma unroll
            for (int i = 0; i < 8; i++) {
                ulonglong2 a = *(const ulonglong2*)(xb + i * GST + k4 * 4);
                #pragma unroll
                for (int j = 0; j < 4; j++) {
                    fma2(acc[i][j], a.x, w[j].x);
                    fma2(acc[i][j], a.y, w[j].y);
                }
            }
        }
        __syncthreads();
    }

    float bv4[4];
    #pragma unroll
    for (int j = 0; j < 4; j++) bv4[j] = bias[n0 + tx + 16 * j];

    float ss[8];
    #pragma unroll
    for (int i = 0; i < 8; i++) {
        ss[i] = 0.f;
        size_t mrow = (size_t)(m0 + ty * 8 + i) * UDIM;
        #pragma unroll
        for (int j = 0; j < 4; j++) {
            float v = hsum(acc[i][j]) + bv4[j];
            v = v > 0.f ? v : 0.f;
            ss[i] += v * v;
            dst[mrow + n0 + tx + 16 * j] = v;
        }
    }

    // head-norm epilogue (Q & K only): BN=64 == one head's d-slice
    if (blockIdx.z < 2) {
        float* ndst = (blockIdx.z == 0) ? g_Qn : g_Kn;
        #pragma unroll
        for (int i = 0; i < 8; i++) {
            #pragma unroll
            for (int o = 1; o < 16; o <<= 1)
                ss[i] += __shfl_xor_sync(0xffffffffu, ss[i], o);
        }
        if (tx == 0) {
            int base = (n0 >> 6) * (BDIM * LSEQ) + m0 + ty * 8;
            #pragma unroll
            for (int i = 0; i < 8; i++) ndst[base + i] = ss[i];
        }
    }
}

// ---------------- kernel 2: query mask ----------------
__global__ void qm_kernel(const float* __restrict__ q_in) {
    int warp = (blockIdx.x * blockDim.x + threadIdx.x) >> 5;
    int lane = threadIdx.x & 31;
    if (warp >= BDIM * LSEQ) return;
    float s = 0.f;
    for (int e = lane; e < UDIM; e += 32) s += q_in[(size_t)warp * UDIM + e];
    #pragma unroll
    for (int o = 16; o; o >>= 1) s += __shfl_xor_sync(0xffffffffu, s, o);
    if (lane == 0) g_qm[warp] = (s != 0.f) ? 1.f : 0.f;
}

// ---------------- kernel 3: fused euclidean attention (MUFU-free) ----------
// Exact R3 structure: 64 q-rows x hb, 256 thr, 1 block/SM, 8 k-tiles of 64,
// 3-buffer cp.async rotation, fixed-max softmax. Norms hoisted to GEMM.
#define A_QST 64
#define A_KST 68
#define A_SST 68
#define A_KVSZ (64 * A_KST)
#define AOFF_Q  0
#define AOFF_KV (64 * A_QST)                      // 4096
#define AOFF_SS (AOFF_KV + 3 * A_KVSZ)            // 17152
#define AOFF_KN (AOFF_SS + 64 * A_SST)            // 21504
#define AOFF_QQ (AOFF_KN + 2 * 64)                // 21632
#define ATTN_SMEM_FLOATS (AOFF_QQ + 64)           // 21696
#define ATTN_SMEM_BYTES (ATTN_SMEM_FLOATS * 4)    // 86784

__global__ __launch_bounds__(256, 1)
void attn_kernel(float* __restrict__ out, float* __restrict__ score_out) {
    extern __shared__ float smf[];
    float* Qs = smf + AOFF_Q;
    float* KV = smf + AOFF_KV;
    float* Ss = smf + AOFF_SS;
    float* kn_s = smf + AOFF_KN;     // [2][64]
    float* qq_s = smf + AOFF_QQ;

    const int tid = threadIdx.x;
    const int ty = tid >> 4;      // 0..15 -> 4 q-rows each
    const int tx = tid & 15;      // k-cols {tx + 16j} / d-cols tx*4..+3
    const int q0 = blockIdx.x * 64;
    const int hb = blockIdx.y;
    const int h = hb >> 2;        // hb = h*BDIM + b
    const int b = hb & 3;

    const float* Qg = g_Q + ((size_t)(b * LSEQ + q0)) * UDIM + h * DDIM;
    const float* Kg = g_K + ((size_t)(b * LSEQ)) * UDIM + h * DDIM;
    const float* Vg = g_V + ((size_t)(b * LSEQ)) * UDIM + h * DDIM;
    const float* Qn = g_Qn + (size_t)h * (BDIM * LSEQ) + b * LSEQ + q0;
    const float* Kn = g_Kn + (size_t)h * (BDIM * LSEQ) + b * LSEQ;

    auto load_v = [&](const float* src, float* dst) {
        #pragma unroll
        for (int i = 0; i < 4; i++) {
            int lin = tid + i * 256;
            int r = lin >> 4, c = lin & 15;
            cpa16(dst + r * A_KST + c * 4, src + (size_t)r * UDIM + c * 4);
        }
    };
    auto load_k = [&](int t, float* dst) {
        load_v(Kg + (size_t)t * 64 * UDIM, dst);
        if (tid < 16) cpa16(kn_s + (t & 1) * 64 + tid * 4, Kn + t * 64 + tid * 4);
    };

    // group 0: Q + qq + K0 + kn0
    #pragma unroll
    for (int i = 0; i < 4; i++) {
        int lin = tid + i * 256;
        int r = lin >> 4, c = lin & 15;
        cpa16(Qs + r * A_QST + c * 4, Qg + (size_t)r * UDIM + c * 4);
    }
    if (tid < 16) cpa16(qq_s + tid * 4, Qn + tid * 4);
    load_k(0, KV + 0 * A_KVSZ);
    CPA_COMMIT();                                   // idx 0
    load_v(Vg, KV + 1 * A_KVSZ);
    CPA_COMMIT();                                   // idx 1: V0
    load_k(1, KV + 2 * A_KVSZ);
    CPA_COMMIT();                                   // idx 2: K1

    float qm_r[4], l_acc[4];
    #pragma unroll
    for (int i = 0; i < 4; i++) {
        qm_r[i] = g_qm[b * LSEQ + q0 + ty * 4 + i];
        l_acc[i] = 0.f;
    }

    CPA_WAIT(2);
    __syncthreads();

    float qq_r[4];
    #pragma unroll
    for (int i = 0; i < 4; i++) qq_r[i] = qq_s[ty * 4 + i];

    ull oacc[4][2] = {};

    for (int t = 0; t < 8; t++) {
        float* Kb = KV + ((2 * t) % 3) * A_KVSZ;
        float* Vb = KV + ((2 * t + 1) % 3) * A_KVSZ;

        if (t >= 1 && t <= 6) load_k(t + 1, KV + ((2 * t + 2) % 3) * A_KVSZ);
        CPA_COMMIT();
        CPA_WAIT(2);                                // K_t (+kn_t) ready
        __syncthreads();

        // ---- S compute (R3-style full dot[4][4]) ----
        ull dot[4][4] = {};
        #pragma unroll
        for (int d4 = 0; d4 < 16; d4++) {
            ulonglong2 kv4[4];
            #pragma unroll
            for (int j = 0; j < 4; j++)
                kv4[j] = *(const ulonglong2*)(Kb + (tx + 16 * j) * A_KST + d4 * 4);
            #pragma unroll
            for (int i = 0; i < 4; i++) {
                ulonglong2 a = *(const ulonglong2*)(Qs + (ty * 4 + i) * A_QST + d4 * 4);
                #pragma unroll
                for (int j = 0; j < 4; j++) {
                    fma2(dot[i][j], a.x, kv4[j].x);
                    fma2(dot[i][j], a.y, kv4[j].y);
                }
            }
        }
        float kk[4];
        #pragma unroll
        for (int j = 0; j < 4; j++) kk[j] = kn_s[(t & 1) * 64 + tx + 16 * j];

        #pragma unroll
        for (int i = 0; i < 4; i++) {
            int r = ty * 4 + i;
            size_t srow = ((size_t)(hb * LSEQ + q0 + r)) * LSEQ + t * 64;
            #pragma unroll
            for (int j = 0; j < 4; j++) {
                float d2 = fmaxf(qq_r[i] + kk[j] - 2.f * hsum(dot[i][j]), 1e-12f);
                float sq = sqrt_nm(d2);
                score_out[srow + tx + 16 * j] = (-0.125f * sq) * qm_r[i];
                float p = exp2_poly(-0.18033688f * sq);   // exp(-sq/8)
                Ss[r * A_SST + tx + 16 * j] = p;
                l_acc[i] += p;
            }
        }
        __syncthreads();     // Ss ready; Kb fully consumed

        if (t < 7) load_v(Vg + (size_t)(t + 1) * 64 * UDIM, KV + ((2 * t) % 3) * A_KVSZ);
        CPA_COMMIT();
        CPA_WAIT(2);                                // V_t ready
        __syncthreads();

        // ---- PV accumulate ----
        #pragma unroll
        for (int k4 = 0; k4 < 16; k4++) {
            float4 p4[4];
            #pragma unroll
            for (int i = 0; i < 4; i++)
                p4[i] = *(const float4*)(Ss + (ty * 4 + i) * A_SST + k4 * 4);
            #pragma unroll
            for (int kk_ = 0; kk_ < 4; kk_++) {
                ulonglong2 v = *(const ulonglong2*)(Vb + (k4 * 4 + kk_) * A_KST + tx * 4);
                #pragma unroll
                for (int i = 0; i < 4; i++) {
                    float pe = ((const float*)&p4[i])[kk_];
                    ull p2 = pk2(pe, pe);
                    fma2(oacc[i][0], p2, v.x);
                    fma2(oacc[i][1], p2, v.y);
                }
            }
        }
        __syncthreads();
    }

    #pragma unroll
    for (int i = 0; i < 4; i++) {
        #pragma unroll
        for (int o = 1; o < 16; o <<= 1)
            l_acc[i] += __shfl_xor_sync(0xffffffffu, l_acc[i], o);
    }

    #pragma unroll
    for (int i = 0; i < 4; i++) {
        int r = ty * 4 + i;
        float scale = qm_r[i] / l_acc[i];
        float2 f0 = upk(oacc[i][0]);
        float2 f1 = upk(oacc[i][1]);
        float4 o;
        o.x = f0.x * scale; o.y = f0.y * scale;
        o.z = f1.x * scale; o.w = f1.y * scale;
        *(float4*)(out + ((size_t)(b * LSEQ + q0 + r)) * UDIM + h * DDIM + tx * 4) = o;
    }
}

// ---------------- launcher ----------------
extern "C" void kernel_launch(void* const* d_in, const int* in_sizes, int n_in,
                              void* d_out, int out_size) {
    (void)in_sizes; (void)n_in; (void)out_size;
    const float* queries = (const float*)d_in[0];
    const float* keys    = (const float*)d_in[1];
    const float* values  = (const float*)d_in[2];
    const float* Wq = (const float*)d_in[3];
    const float* bq = (const float*)d_in[4];
    const float* Wk = (const float*)d_in[5];
    const float* bk = (const float*)d_in[6];
    const float* Wv = (const float*)d_in[7];
    const float* bv = (const float*)d_in[8];

    float* out_ptr   = (float*)d_out;
    float* score_ptr = out_ptr + (size_t)BDIM * LSEQ * UDIM;

    cudaFuncSetAttribute(qkv_gemm_kernel, cudaFuncAttributeMaxDynamicSharedMemorySize,
                         GEMM_SMEM_BYTES);
    cudaFuncSetAttribute(attn_kernel, cudaFuncAttributeMaxDynamicSharedMemorySize,
                         ATTN_SMEM_BYTES);

    dim3 tgrid(UDIM / 32, UDIM / 32, 3);
    transpose_w_kernel<<<tgrid, 256>>>(Wq, Wk, Wv);

    dim3 ggrid(BDIM * LSEQ / GBM, UDIM / GBN, 3);
    qkv_gemm_kernel<<<ggrid, 256, GEMM_SMEM_BYTES>>>(queries, keys, values, bq, bk, bv);

    qm_kernel<<<(BDIM * LSEQ * 32) / 256, 256>>>(queries);

    dim3 agrid(LSEQ / 64, HBDIM);
    attn_kernel<<<agrid, 256, ATTN_SMEM_BYTES>>>(out_ptr, score_ptr);
}

// round 8
// speedup vs baseline: 1.7829x; 1.3257x over previous
#include <cuda_runtime.h>
#include <cuda_bf16.h>
#include <cstdint>

#define LSEQ 512
#define UDIM 512
#define BDIM 4
#define HDIM 8
#define DDIM 64
#define HBDIM 32

typedef unsigned long long ull;

// ---------------- scratch (device globals, no allocation) ----------------
__device__ float g_Q[BDIM * LSEQ * UDIM];
__device__ float g_K[BDIM * LSEQ * UDIM];
__device__ float g_V[BDIM * LSEQ * UDIM];
__device__ float g_qm[BDIM * LSEQ];
__device__ float g_Qn[HDIM * BDIM * LSEQ];     // ||Q_head||^2 per (h, b*L+row)
__device__ float g_Kn[HDIM * BDIM * LSEQ];
// bf16 2-way splits: X inputs [z][m][u], W transposed [z][n][k]
__device__ __nv_bfloat16 g_Xh[3 * BDIM * LSEQ * UDIM];
__device__ __nv_bfloat16 g_Xl[3 * BDIM * LSEQ * UDIM];
__device__ __nv_bfloat16 g_Wh[3 * UDIM * UDIM];
__device__ __nv_bfloat16 g_Wl[3 * UDIM * UDIM];

// ---------------- helpers ----------------
__device__ __forceinline__ void fma2(ull& d, ull a, ull b) {
    asm("fma.rn.f32x2 %0, %1, %2, %0;" : "+l"(d) : "l"(a), "l"(b));
}
__device__ __forceinline__ ull pk2(float x, float y) {
    ull r; asm("mov.b64 %0, {%1, %2};" : "=l"(r) : "f"(x), "f"(y)); return r;
}
__device__ __forceinline__ float2 upk(ull v) {
    float2 f; asm("mov.b64 {%0, %1}, %2;" : "=f"(f.x), "=f"(f.y) : "l"(v)); return f;
}
__device__ __forceinline__ float hsum(ull v) { float2 f = upk(v); return f.x + f.y; }

__device__ __forceinline__ float sqrt_nm(float x) {
    float r = __int_as_float(0x5f3759df - (__float_as_int(x) >> 1));
    r = r * (1.5f - 0.5f * x * r * r);
    r = r * (1.5f - 0.5f * x * r * r);
    return x * r;
}
__device__ __forceinline__ float exp2_poly(float y) {
    y = fmaxf(y, -120.f);
    float fn = y + 12582912.f;
    int ib = __float_as_int(fn);
    float n = fn - 12582912.f;
    float f = y - n;
    float scale = __int_as_float((ib - 0x4B400000 + 127) << 23);
    float p = 0.0013333558f;
    p = fmaf(p, f, 0.0096181291f);
    p = fmaf(p, f, 0.0555041087f);
    p = fmaf(p, f, 0.2402265069f);
    p = fmaf(p, f, 0.6931471806f);
    p = fmaf(p, f, 1.0f);
    return scale * p;
}

__device__ __forceinline__ void cpa16(void* sdst, const void* gsrc) {
    uint32_t s = (uint32_t)__cvta_generic_to_shared(sdst);
    asm volatile("cp.async.cg.shared.global [%0], [%1], 16;" :: "r"(s), "l"(gsrc));
}
#define CPA_COMMIT() asm volatile("cp.async.commit_group;")
#define CPA_WAIT(n)  asm volatile("cp.async.wait_group %0;" :: "n"(n))

__device__ __forceinline__ void ldsm4(uint32_t* r, uint32_t addr) {
    asm volatile("ldmatrix.sync.aligned.m8n8.x4.shared.b16 {%0,%1,%2,%3}, [%4];"
                 : "=r"(r[0]), "=r"(r[1]), "=r"(r[2]), "=r"(r[3]) : "r"(addr));
}
__device__ __forceinline__ void mma16816(float* d, const uint32_t* a, const uint32_t* b) {
    asm volatile(
        "mma.sync.aligned.m16n8k16.row.col.f32.bf16.bf16.f32 "
        "{%0,%1,%2,%3}, {%4,%5,%6,%7}, {%8,%9}, {%0,%1,%2,%3};"
        : "+f"(d[0]), "+f"(d[1]), "+f"(d[2]), "+f"(d[3])
        : "r"(a[0]), "r"(a[1]), "r"(a[2]), "r"(a[3]), "r"(b[0]), "r"(b[1]));
}
__device__ __forceinline__ unsigned short bfbits(__nv_bfloat16 h) {
    return *reinterpret_cast<unsigned short*>(&h);
}
__device__ __forceinline__ void split1(float x, unsigned short& h, unsigned short& l) {
    __nv_bfloat16 hb = __float2bfloat16_rn(x);
    float lf = x - __bfloat162float(hb);
    __nv_bfloat16 lb = __float2bfloat16_rn(lf);
    h = bfbits(hb); l = bfbits(lb);
}

// ---------------- kernel A: split X inputs to bf16 hi/lo ----------------
__global__ void split_x_kernel(const float* __restrict__ q,
                               const float* __restrict__ k,
                               const float* __restrict__ v) {
    int z = blockIdx.y;
    const float* src = (z == 0) ? q : (z == 1) ? k : v;
    __nv_bfloat16* dh = g_Xh + (size_t)z * (BDIM * LSEQ * UDIM);
    __nv_bfloat16* dl = g_Xl + (size_t)z * (BDIM * LSEQ * UDIM);
    size_t i = ((size_t)blockIdx.x * 256 + threadIdx.x) * 4;
    float4 x = *(const float4*)(src + i);
    ushort4 h, l;
    split1(x.x, h.x, l.x);
    split1(x.y, h.y, l.y);
    split1(x.z, h.z, l.z);
    split1(x.w, h.w, l.w);
    *(ushort4*)(dh + i) = h;
    *(ushort4*)(dl + i) = l;
}

// ---------------- kernel B: transpose + split W -> [n][k] bf16 hi/lo ------
__global__ void split_w_kernel(const float* __restrict__ Wq,
                               const float* __restrict__ Wk,
                               const float* __restrict__ Wv) {
    __shared__ float t[32][33];
    int z = blockIdx.z;
    const float* W = (z == 0) ? Wq : (z == 1) ? Wk : Wv;
    __nv_bfloat16* dh = g_Wh + (size_t)z * UDIM * UDIM;
    __nv_bfloat16* dl = g_Wl + (size_t)z * UDIM * UDIM;
    int k0 = blockIdx.x * 32;
    int n0 = blockIdx.y * 32;
    int tx = threadIdx.x & 31, ty = threadIdx.x >> 5;
    #pragma unroll
    for (int i = 0; i < 4; i++) {
        int r = ty + i * 8;
        t[r][tx] = W[(size_t)(k0 + r) * UDIM + n0 + tx];
    }
    __syncthreads();
    #pragma unroll
    for (int i = 0; i < 4; i++) {
        int r = ty + i * 8;      // n-offset
        unsigned short h, l;
        split1(t[tx][r], h, l);
        size_t off = (size_t)(n0 + r) * UDIM + k0 + tx;
        *reinterpret_cast<unsigned short*>(dh + off) = h;
        *reinterpret_cast<unsigned short*>(dl + off) = l;
    }
}

// ---------------- kernel 1: tensor-core GEMM (bf16 split-2) ----------------
// C[2048x512] = relu(X @ W + b), via D += Xh*Wh + Xh*Wl + Xl*Wh.
// Tile M=128, N=128, K-chunk 64. 256 thr = 8 warps (4 m x 2 n), warp 32x64.
// SMEM tiles [128 rows][64 bf16] with chunk-XOR swizzle -> conflict-free ldmatrix.
#define TILE_E (128 * 64)          // bf16 elements per tile
#define STAGE_E (4 * TILE_E)       // Ah, Al, Bh, Bl
#define GEMM_SMEM_BYTES (2 * STAGE_E * 2)   // 131072

__global__ __launch_bounds__(256, 1)
void qkv_gemm_mma(const float* __restrict__ bq,
                  const float* __restrict__ bk,
                  const float* __restrict__ bv) {
    extern __shared__ __nv_bfloat16 smb[];
    const int z = blockIdx.z;
    const __nv_bfloat16* Xh = g_Xh + (size_t)z * (BDIM * LSEQ * UDIM);
    const __nv_bfloat16* Xl = g_Xl + (size_t)z * (BDIM * LSEQ * UDIM);
    const __nv_bfloat16* Wh = g_Wh + (size_t)z * UDIM * UDIM;
    const __nv_bfloat16* Wl = g_Wl + (size_t)z * UDIM * UDIM;
    const float* bias = (z == 0) ? bq : (z == 1) ? bk : bv;
    float* dst = (z == 0) ? g_Q : (z == 1) ? g_K : g_V;

    const int tid = threadIdx.x;
    const int wid = tid >> 5;
    const int lane = tid & 31;
    const int wm = wid & 3;         // warp m: 32 rows
    const int wn = wid >> 2;        // warp n: 64 cols (= one head)
    const int m0 = blockIdx.x * 128;
    const int n0 = blockIdx.y * 128;

    // cp.async issue of one stage (4 tiles x 1024 chunks, 4 chunks/thread/tile)
    auto issue = [&](int kc, int buf) {
        __nv_bfloat16* st = smb + buf * STAGE_E;
        const __nv_bfloat16* srcs[4] = {Xh, Xl, Wh, Wl};
        const int rows0[4] = {m0, m0, n0, n0};
        #pragma unroll
        for (int tile = 0; tile < 4; tile++) {
            const __nv_bfloat16* src = srcs[tile];
            #pragma unroll
            for (int i = 0; i < 4; i++) {
                int q = tid + i * 256;         // 0..1023
                int r = q >> 3, c = q & 7;
                cpa16(st + tile * TILE_E + r * 64 + ((c ^ (r & 7)) << 3),
                      src + (size_t)(rows0[tile] + r) * UDIM + kc * 64 + c * 8);
            }
        }
        CPA_COMMIT();
    };

    float d[2][8][4];
    #pragma unroll
    for (int mf = 0; mf < 2; mf++)
        #pragma unroll
        for (int nf = 0; nf < 8; nf++)
            #pragma unroll
            for (int e = 0; e < 4; e++) d[mf][nf][e] = 0.f;

    const uint32_t smem_u = (uint32_t)__cvta_generic_to_shared(smb);
    // ldmatrix lane addressing
    const int arow = wm * 32 + (lane & 15);          // + mf*16
    const int ahalf = lane >> 4;                     // chunk half
    const int asw = arow & 7;                        // swizzle key (same for +16)
    const int brow = wn * 64 + (lane & 7) + ((lane >> 4) << 3);   // + ng*16
    const int bhalf = (lane >> 3) & 1;
    const int bsw = brow & 7;

    issue(0, 0);

    for (int kc = 0; kc < 8; kc++) {
        if (kc < 7) { issue(kc + 1, (kc + 1) & 1); CPA_WAIT(1); }
        else        { CPA_WAIT(0); }
        __syncthreads();

        const uint32_t stage_b = smem_u + ((kc & 1) ? STAGE_E * 2 : 0);

        #pragma unroll
        for (int k16 = 0; k16 < 4; k16++) {
            uint32_t ah[2][4], al[2][4];
            #pragma unroll
            for (int mf = 0; mf < 2; mf++) {
                uint32_t aoff = (uint32_t)((arow + mf * 16) * 64 +
                                           (((k16 * 2 + ahalf) ^ asw) << 3)) * 2;
                ldsm4(ah[mf], stage_b + 0 * TILE_E * 2 + aoff);
                ldsm4(al[mf], stage_b + 1 * TILE_E * 2 + aoff);
            }
            uint32_t bh[16], bl[16];
            #pragma unroll
            for (int ng = 0; ng < 4; ng++) {
                uint32_t boff = (uint32_t)((brow + ng * 16) * 64 +
                                           (((k16 * 2 + bhalf) ^ bsw) << 3)) * 2;
                ldsm4(&bh[ng * 4], stage_b + 2 * TILE_E * 2 + boff);
                ldsm4(&bl[ng * 4], stage_b + 3 * TILE_E * 2 + boff);
            }
            #pragma unroll
            for (int mf = 0; mf < 2; mf++)
                #pragma unroll
                for (int nf = 0; nf < 8; nf++) {
                    mma16816(d[mf][nf], ah[mf], &bh[nf * 2]);   // hi*hi
                    mma16816(d[mf][nf], ah[mf], &bl[nf * 2]);   // hi*lo
                    mma16816(d[mf][nf], al[mf], &bh[nf * 2]);   // lo*hi
                }
        }
        __syncthreads();
    }

    // epilogue: bias + relu + store fp32 + head row-norms (one head per warp)
    #pragma unroll
    for (int mf = 0; mf < 2; mf++) {
        int r0 = m0 + wm * 32 + mf * 16 + (lane >> 2);
        int r1 = r0 + 8;
        float ssA = 0.f, ssB = 0.f;
        #pragma unroll
        for (int nf = 0; nf < 8; nf++) {
            int col = n0 + wn * 64 + nf * 8 + (lane & 3) * 2;
            float2 bv2 = *(const float2*)(bias + col);
            float v0 = d[mf][nf][0] + bv2.x; v0 = v0 > 0.f ? v0 : 0.f;
            float v1 = d[mf][nf][1] + bv2.y; v1 = v1 > 0.f ? v1 : 0.f;
            float v2 = d[mf][nf][2] + bv2.x; v2 = v2 > 0.f ? v2 : 0.f;
            float v3 = d[mf][nf][3] + bv2.y; v3 = v3 > 0.f ? v3 : 0.f;
            *(float2*)(dst + (size_t)r0 * UDIM + col) = make_float2(v0, v1);
            *(float2*)(dst + (size_t)r1 * UDIM + col) = make_float2(v2, v3);
            ssA += v0 * v0 + v1 * v1;
            ssB += v2 * v2 + v3 * v3;
        }
        if (z < 2) {
            ssA += __shfl_xor_sync(0xffffffffu, ssA, 1);
            ssA += __shfl_xor_sync(0xffffffffu, ssA, 2);
            ssB += __shfl_xor_sync(0xffffffffu, ssB, 1);
            ssB += __shfl_xor_sync(0xffffffffu, ssB, 2);
            if ((lane & 3) == 0) {
                float* ndst = (z == 0) ? g_Qn : g_Kn;
                int h = blockIdx.y * 2 + wn;
                ndst[h * (BDIM * LSEQ) + r0] = ssA;
                ndst[h * (BDIM * LSEQ) + r1] = ssB;
            }
        }
    }
}

// ---------------- kernel 2: query mask ----------------
__global__ void qm_kernel(const float* __restrict__ q_in) {
    int warp = (blockIdx.x * blockDim.x + threadIdx.x) >> 5;
    int lane = threadIdx.x & 31;
    if (warp >= BDIM * LSEQ) return;
    float s = 0.f;
    for (int e = lane; e < UDIM; e += 32) s += q_in[(size_t)warp * UDIM + e];
    #pragma unroll
    for (int o = 16; o; o >>= 1) s += __shfl_xor_sync(0xffffffffu, s, o);
    if (lane == 0) g_qm[warp] = (s != 0.f) ? 1.f : 0.f;
}

// ---------------- kernel 3: fused euclidean attention (R6, unchanged) -----
#define A_QST 64
#define A_KST 68
#define A_SST 68
#define A_KVSZ (64 * A_KST)
#define AOFF_Q  0
#define AOFF_KV (64 * A_QST)
#define AOFF_SS (AOFF_KV + 3 * A_KVSZ)
#define AOFF_KN (AOFF_SS + 64 * A_SST)
#define AOFF_QQ (AOFF_KN + 2 * 64)
#define ATTN_SMEM_FLOATS (AOFF_QQ + 64)
#define ATTN_SMEM_BYTES (ATTN_SMEM_FLOATS * 4)

__global__ __launch_bounds__(256, 1)
void attn_kernel(float* __restrict__ out, float* __restrict__ score_out) {
    extern __shared__ float smf[];
    float* Qs = smf + AOFF_Q;
    float* KV = smf + AOFF_KV;
    float* Ss = smf + AOFF_SS;
    float* kn_s = smf + AOFF_KN;
    float* qq_s = smf + AOFF_QQ;

    const int tid = threadIdx.x;
    const int ty = tid >> 4;
    const int tx = tid & 15;
    const int q0 = blockIdx.x * 64;
    const int hb = blockIdx.y;
    const int h = hb >> 2;
    const int b = hb & 3;

    const float* Qg = g_Q + ((size_t)(b * LSEQ + q0)) * UDIM + h * DDIM;
    const float* Kg = g_K + ((size_t)(b * LSEQ)) * UDIM + h * DDIM;
    const float* Vg = g_V + ((size_t)(b * LSEQ)) * UDIM + h * DDIM;
    const float* Qn = g_Qn + (size_t)h * (BDIM * LSEQ) + b * LSEQ + q0;
    const float* Kn = g_Kn + (size_t)h * (BDIM * LSEQ) + b * LSEQ;

    auto load_v = [&](const float* src, float* dst) {
        #pragma unroll
        for (int i = 0; i < 4; i++) {
            int lin = tid + i * 256;
            int r = lin >> 4, c = lin & 15;
            cpa16(dst + r * A_KST + c * 4, src + (size_t)r * UDIM + c * 4);
        }
    };
    auto load_k = [&](int t, float* dst) {
        load_v(Kg + (size_t)t * 64 * UDIM, dst);
        if (tid < 16) cpa16(kn_s + (t & 1) * 64 + tid * 4, Kn + t * 64 + tid * 4);
    };

    #pragma unroll
    for (int i = 0; i < 4; i++) {
        int lin = tid + i * 256;
        int r = lin >> 4, c = lin & 15;
        cpa16(Qs + r * A_QST + c * 4, Qg + (size_t)r * UDIM + c * 4);
    }
    if (tid < 16) cpa16(qq_s + tid * 4, Qn + tid * 4);
    load_k(0, KV + 0 * A_KVSZ);
    CPA_COMMIT();
    load_v(Vg, KV + 1 * A_KVSZ);
    CPA_COMMIT();
    load_k(1, KV + 2 * A_KVSZ);
    CPA_COMMIT();

    float qm_r[4], l_acc[4];
    #pragma unroll
    for (int i = 0; i < 4; i++) {
        qm_r[i] = g_qm[b * LSEQ + q0 + ty * 4 + i];
        l_acc[i] = 0.f;
    }

    CPA_WAIT(2);
    __syncthreads();

    float qq_r[4];
    #pragma unroll
    for (int i = 0; i < 4; i++) qq_r[i] = qq_s[ty * 4 + i];

    ull oacc[4][2] = {};

    for (int t = 0; t < 8; t++) {
        float* Kb = KV + ((2 * t) % 3) * A_KVSZ;
        float* Vb = KV + ((2 * t + 1) % 3) * A_KVSZ;

        if (t >= 1 && t <= 6) load_k(t + 1, KV + ((2 * t + 2) % 3) * A_KVSZ);
        CPA_COMMIT();
        CPA_WAIT(2);
        __syncthreads();

        ull dot[4][4] = {};
        #pragma unroll
        for (int d4 = 0; d4 < 16; d4++) {
            ulonglong2 kv4[4];
            #pragma unroll
            for (int j = 0; j < 4; j++)
                kv4[j] = *(const ulonglong2*)(Kb + (tx + 16 * j) * A_KST + d4 * 4);
            #pragma unroll
            for (int i = 0; i < 4; i++) {
                ulonglong2 a = *(const ulonglong2*)(Qs + (ty * 4 + i) * A_QST + d4 * 4);
                #pragma unroll
                for (int j = 0; j < 4; j++) {
                    fma2(dot[i][j], a.x, kv4[j].x);
                    fma2(dot[i][j], a.y, kv4[j].y);
                }
            }
        }
        float kk[4];
        #pragma unroll
        for (int j = 0; j < 4; j++) kk[j] = kn_s[(t & 1) * 64 + tx + 16 * j];

        #pragma unroll
        for (int i = 0; i < 4; i++) {
            int r = ty * 4 + i;
            size_t srow = ((size_t)(hb * LSEQ + q0 + r)) * LSEQ + t * 64;
            #pragma unroll
            for (int j = 0; j < 4; j++) {
                float d2 = fmaxf(qq_r[i] + kk[j] - 2.f * hsum(dot[i][j]), 1e-12f);
                float sq = sqrt_nm(d2);
                score_out[srow + tx + 16 * j] = (-0.125f * sq) * qm_r[i];
                float p = exp2_poly(-0.18033688f * sq);
                Ss[r * A_SST + tx + 16 * j] = p;
                l_acc[i] += p;
            }
        }
        __syncthreads();

        if (t < 7) load_v(Vg + (size_t)(t + 1) * 64 * UDIM, KV + ((2 * t) % 3) * A_KVSZ);
        CPA_COMMIT();
        CPA_WAIT(2);
        __syncthreads();

        #pragma unroll
        for (int k4 = 0; k4 < 16; k4++) {
            float4 p4[4];
            #pragma unroll
            for (int i = 0; i < 4; i++)
                p4[i] = *(const float4*)(Ss + (ty * 4 + i) * A_SST + k4 * 4);
            #pragma unroll
            for (int kk_ = 0; kk_ < 4; kk_++) {
                ulonglong2 v = *(const ulonglong2*)(Vb + (k4 * 4 + kk_) * A_KST + tx * 4);
                #pragma unroll
                for (int i = 0; i < 4; i++) {
                    float pe = ((const float*)&p4[i])[kk_];
                    ull p2 = pk2(pe, pe);
                    fma2(oacc[i][0], p2, v.x);
                    fma2(oacc[i][1], p2, v.y);
                }
            }
        }
        __syncthreads();
    }

    #pragma unroll
    for (int i = 0; i < 4; i++) {
        #pragma unroll
        for (int o = 1; o < 16; o <<= 1)
            l_acc[i] += __shfl_xor_sync(0xffffffffu, l_acc[i], o);
    }

    #pragma unroll
    for (int i = 0; i < 4; i++) {
        int r = ty * 4 + i;
        float scale = qm_r[i] / l_acc[i];
        float2 f0 = upk(oacc[i][0]);
        float2 f1 = upk(oacc[i][1]);
        float4 o;
        o.x = f0.x * scale; o.y = f0.y * scale;
        o.z = f1.x * scale; o.w = f1.y * scale;
        *(float4*)(out + ((size_t)(b * LSEQ + q0 + r)) * UDIM + h * DDIM + tx * 4) = o;
    }
}

// ---------------- launcher ----------------
extern "C" void kernel_launch(void* const* d_in, const int* in_sizes, int n_in,
                              void* d_out, int out_size) {
    (void)in_sizes; (void)n_in; (void)out_size;
    const float* queries = (const float*)d_in[0];
    const float* keys    = (const float*)d_in[1];
    const float* values  = (const float*)d_in[2];
    const float* Wq = (const float*)d_in[3];
    const float* bq = (const float*)d_in[4];
    const float* Wk = (const float*)d_in[5];
    const float* bk = (const float*)d_in[6];
    const float* Wv = (const float*)d_in[7];
    const float* bv = (const float*)d_in[8];

    float* out_ptr   = (float*)d_out;
    float* score_ptr = out_ptr + (size_t)BDIM * LSEQ * UDIM;

    cudaFuncSetAttribute(qkv_gemm_mma, cudaFuncAttributeMaxDynamicSharedMemorySize,
                         GEMM_SMEM_BYTES);
    cudaFuncSetAttribute(attn_kernel, cudaFuncAttributeMaxDynamicSharedMemorySize,
                         ATTN_SMEM_BYTES);

    // prep: split inputs + transposed weights into bf16 hi/lo
    dim3 sxgrid((BDIM * LSEQ * UDIM) / (256 * 4), 3);
    split_x_kernel<<<sxgrid, 256>>>(queries, keys, values);
    dim3 swgrid(UDIM / 32, UDIM / 32, 3);
    split_w_kernel<<<swgrid, 256>>>(Wq, Wk, Wv);

    // tensor-core QKV projection
    dim3 ggrid(BDIM * LSEQ / 128, UDIM / 128, 3);
    qkv_gemm_mma<<<ggrid, 256, GEMM_SMEM_BYTES>>>(bq, bk, bv);

    qm_kernel<<<(BDIM * LSEQ * 32) / 256, 256>>>(queries);

    dim3 agrid(LSEQ / 64, HBDIM);
    attn_kernel<<<agrid, 256, ATTN_SMEM_BYTES>>>(out_ptr, score_ptr);
}

// round 9
// speedup vs baseline: 2.8860x; 1.6187x over previous
#include <cuda_runtime.h>
#include <cuda_bf16.h>
#include <cstdint>

#define LSEQ 512
#define UDIM 512
#define BDIM 4
#define HDIM 8
#define DDIM 64
#define HBDIM 32

typedef unsigned long long ull;

// ---------------- scratch (device globals, no allocation) ----------------
__device__ float g_qm[BDIM * LSEQ];
__device__ float g_Qn[HDIM * BDIM * LSEQ];     // ||Q_head||^2 per (h, b*L+row)
__device__ float g_Kn[HDIM * BDIM * LSEQ];
// bf16 2-way splits of GEMM inputs: X [z][m][u], W transposed [z][n][k]
__device__ __nv_bfloat16 g_Xh[3 * BDIM * LSEQ * UDIM];
__device__ __nv_bfloat16 g_Xl[3 * BDIM * LSEQ * UDIM];
__device__ __nv_bfloat16 g_Wh[3 * UDIM * UDIM];
__device__ __nv_bfloat16 g_Wl[3 * UDIM * UDIM];
// bf16 2-way splits of the PROJECTED Q/K/V (GEMM output), [z][m][u]
__device__ __nv_bfloat16 g_Ph[3 * BDIM * LSEQ * UDIM];
__device__ __nv_bfloat16 g_Pl[3 * BDIM * LSEQ * UDIM];

// ---------------- helpers ----------------
__device__ __forceinline__ float sqrt_nm(float x) {
    float r = __int_as_float(0x5f3759df - (__float_as_int(x) >> 1));
    r = r * (1.5f - 0.5f * x * r * r);
    r = r * (1.5f - 0.5f * x * r * r);
    return x * r;
}
__device__ __forceinline__ float exp2_poly(float y) {
    y = fmaxf(y, -120.f);
    float fn = y + 12582912.f;
    int ib = __float_as_int(fn);
    float n = fn - 12582912.f;
    float f = y - n;
    float scale = __int_as_float((ib - 0x4B400000 + 127) << 23);
    float p = 0.0013333558f;
    p = fmaf(p, f, 0.0096181291f);
    p = fmaf(p, f, 0.0555041087f);
    p = fmaf(p, f, 0.2402265069f);
    p = fmaf(p, f, 0.6931471806f);
    p = fmaf(p, f, 1.0f);
    return scale * p;
}

__device__ __forceinline__ void cpa16(void* sdst, const void* gsrc) {
    uint32_t s = (uint32_t)__cvta_generic_to_shared(sdst);
    asm volatile("cp.async.cg.shared.global [%0], [%1], 16;" :: "r"(s), "l"(gsrc));
}
#define CPA_COMMIT() asm volatile("cp.async.commit_group;")
#define CPA_WAIT(n)  asm volatile("cp.async.wait_group %0;" :: "n"(n))

__device__ __forceinline__ void ldsm4(uint32_t* r, uint32_t addr) {
    asm volatile("ldmatrix.sync.aligned.m8n8.x4.shared.b16 {%0,%1,%2,%3}, [%4];"
                 : "=r"(r[0]), "=r"(r[1]), "=r"(r[2]), "=r"(r[3]) : "r"(addr));
}
__device__ __forceinline__ void ldsm4t(uint32_t* r, uint32_t addr) {
    asm volatile("ldmatrix.sync.aligned.m8n8.x4.trans.shared.b16 {%0,%1,%2,%3}, [%4];"
                 : "=r"(r[0]), "=r"(r[1]), "=r"(r[2]), "=r"(r[3]) : "r"(addr));
}
__device__ __forceinline__ void mma16816(float* d, const uint32_t* a, const uint32_t* b) {
    asm volatile(
        "mma.sync.aligned.m16n8k16.row.col.f32.bf16.bf16.f32 "
        "{%0,%1,%2,%3}, {%4,%5,%6,%7}, {%8,%9}, {%0,%1,%2,%3};"
        : "+f"(d[0]), "+f"(d[1]), "+f"(d[2]), "+f"(d[3])
        : "r"(a[0]), "r"(a[1]), "r"(a[2]), "r"(a[3]), "r"(b[0]), "r"(b[1]));
}
// pack {lo, hi} floats -> bf16x2 (lo in low half)
__device__ __forceinline__ uint32_t cvt_bf2(float lo, float hi) {
    uint32_t d; asm("cvt.rn.bf16x2.f32 %0, %1, %2;" : "=r"(d) : "f"(hi), "f"(lo)); return d;
}
__device__ __forceinline__ unsigned short bfbits(__nv_bfloat16 h) {
    return *reinterpret_cast<unsigned short*>(&h);
}
__device__ __forceinline__ void split1(float x, unsigned short& h, unsigned short& l) {
    __nv_bfloat16 hb = __float2bfloat16_rn(x);
    float lf = x - __bfloat162float(hb);
    __nv_bfloat16 lb = __float2bfloat16_rn(lf);
    h = bfbits(hb); l = bfbits(lb);
}

// ---------------- kernel A: split X inputs to bf16 hi/lo (+ fused qm) ------
__global__ void split_x_kernel(const float* __restrict__ q,
                               const float* __restrict__ k,
                               const float* __restrict__ v) {
    __shared__ float rs[8];
    int z = blockIdx.y;
    const float* src = (z == 0) ? q : (z == 1) ? k : v;
    __nv_bfloat16* dh = g_Xh + (size_t)z * (BDIM * LSEQ * UDIM);
    __nv_bfloat16* dl = g_Xl + (size_t)z * (BDIM * LSEQ * UDIM);
    size_t i = ((size_t)blockIdx.x * 256 + threadIdx.x) * 4;
    float4 x = *(const float4*)(src + i);
    ushort4 h, l;
    split1(x.x, h.x, l.x);
    split1(x.y, h.y, l.y);
    split1(x.z, h.z, l.z);
    split1(x.w, h.w, l.w);
    *(ushort4*)(dh + i) = h;
    *(ushort4*)(dl + i) = l;

    if (z == 0) {       // query mask: sign(|row sum|); row = 128 threads
        float s = x.x + x.y + x.z + x.w;
        #pragma unroll
        for (int o = 16; o; o >>= 1) s += __shfl_xor_sync(0xffffffffu, s, o);
        if ((threadIdx.x & 31) == 0) rs[threadIdx.x >> 5] = s;
        __syncthreads();
        if ((threadIdx.x & 127) == 0) {
            int w0 = threadIdx.x >> 5;          // 0 or 4
            float t = rs[w0] + rs[w0 + 1] + rs[w0 + 2] + rs[w0 + 3];
            g_qm[i >> 9] = (t != 0.f) ? 1.f : 0.f;
        }
    }
}

// ---------------- kernel B: transpose + split W -> [n][k] bf16 hi/lo ------
__global__ void split_w_kernel(const float* __restrict__ Wq,
                               const float* __restrict__ Wk,
                               const float* __restrict__ Wv) {
    __shared__ float t[32][33];
    int z = blockIdx.z;
    const float* W = (z == 0) ? Wq : (z == 1) ? Wk : Wv;
    __nv_bfloat16* dh = g_Wh + (size_t)z * UDIM * UDIM;
    __nv_bfloat16* dl = g_Wl + (size_t)z * UDIM * UDIM;
    int k0 = blockIdx.x * 32;
    int n0 = blockIdx.y * 32;
    int tx = threadIdx.x & 31, ty = threadIdx.x >> 5;
    #pragma unroll
    for (int i = 0; i < 4; i++) {
        int r = ty + i * 8;
        t[r][tx] = W[(size_t)(k0 + r) * UDIM + n0 + tx];
    }
    __syncthreads();
    #pragma unroll
    for (int i = 0; i < 4; i++) {
        int r = ty + i * 8;
        unsigned short h, l;
        split1(t[tx][r], h, l);
        size_t off = (size_t)(n0 + r) * UDIM + k0 + tx;
        *reinterpret_cast<unsigned short*>(dh + off) = h;
        *reinterpret_cast<unsigned short*>(dl + off) = l;
    }
}

// ---------------- kernel 1: tensor-core GEMM (bf16 split-2) ----------------
// relu(X@W+b) -> bf16 hi/lo projected outputs + head row-norms (Q,K).
#define TILE_E (128 * 64)
#define STAGE_E (4 * TILE_E)
#define GEMM_SMEM_BYTES (2 * STAGE_E * 2)   // 131072

__global__ __launch_bounds__(256, 1)
void qkv_gemm_mma(const float* __restrict__ bq,
                  const float* __restrict__ bk,
                  const float* __restrict__ bv) {
    extern __shared__ __nv_bfloat16 smb[];
    const int z = blockIdx.z;
    const size_t XSZ = (size_t)BDIM * LSEQ * UDIM;
    const __nv_bfloat16* Xh = g_Xh + z * XSZ;
    const __nv_bfloat16* Xl = g_Xl + z * XSZ;
    const __nv_bfloat16* Wh = g_Wh + (size_t)z * UDIM * UDIM;
    const __nv_bfloat16* Wl = g_Wl + (size_t)z * UDIM * UDIM;
    const float* bias = (z == 0) ? bq : (z == 1) ? bk : bv;
    __nv_bfloat16* Ph = g_Ph + z * XSZ;
    __nv_bfloat16* Pl = g_Pl + z * XSZ;

    const int tid = threadIdx.x;
    const int wid = tid >> 5;
    const int lane = tid & 31;
    const int wm = wid & 3;
    const int wn = wid >> 2;
    const int m0 = blockIdx.x * 128;
    const int n0 = blockIdx.y * 128;

    auto issue = [&](int kc, int buf) {
        __nv_bfloat16* st = smb + buf * STAGE_E;
        const __nv_bfloat16* srcs[4] = {Xh, Xl, Wh, Wl};
        const int rows0[4] = {m0, m0, n0, n0};
        #pragma unroll
        for (int tile = 0; tile < 4; tile++) {
            const __nv_bfloat16* src = srcs[tile];
            #pragma unroll
            for (int i = 0; i < 4; i++) {
                int q = tid + i * 256;
                int r = q >> 3, c = q & 7;
                cpa16(st + tile * TILE_E + r * 64 + ((c ^ (r & 7)) << 3),
                      src + (size_t)(rows0[tile] + r) * UDIM + kc * 64 + c * 8);
            }
        }
        CPA_COMMIT();
    };

    float d[2][8][4];
    #pragma unroll
    for (int mf = 0; mf < 2; mf++)
        #pragma unroll
        for (int nf = 0; nf < 8; nf++)
            #pragma unroll
            for (int e = 0; e < 4; e++) d[mf][nf][e] = 0.f;

    const uint32_t smem_u = (uint32_t)__cvta_generic_to_shared(smb);
    const int arow = wm * 32 + (lane & 15);
    const int ahalf = lane >> 4;
    const int asw = arow & 7;
    const int brow = wn * 64 + (lane & 7) + ((lane >> 4) << 3);
    const int bhalf = (lane >> 3) & 1;
    const int bsw = brow & 7;

    issue(0, 0);

    for (int kc = 0; kc < 8; kc++) {
        if (kc < 7) { issue(kc + 1, (kc + 1) & 1); CPA_WAIT(1); }
        else        { CPA_WAIT(0); }
        __syncthreads();

        const uint32_t stage_b = smem_u + ((kc & 1) ? STAGE_E * 2 : 0);

        #pragma unroll
        for (int k16 = 0; k16 < 4; k16++) {
            uint32_t ah[2][4], al[2][4];
            #pragma unroll
            for (int mf = 0; mf < 2; mf++) {
                uint32_t aoff = (uint32_t)((arow + mf * 16) * 64 +
                                           (((k16 * 2 + ahalf) ^ asw) << 3)) * 2;
                ldsm4(ah[mf], stage_b + 0 * TILE_E * 2 + aoff);
                ldsm4(al[mf], stage_b + 1 * TILE_E * 2 + aoff);
            }
            uint32_t bh[16], bl[16];
            #pragma unroll
            for (int ng = 0; ng < 4; ng++) {
                uint32_t boff = (uint32_t)((brow + ng * 16) * 64 +
                                           (((k16 * 2 + bhalf) ^ bsw) << 3)) * 2;
                ldsm4(&bh[ng * 4], stage_b + 2 * TILE_E * 2 + boff);
                ldsm4(&bl[ng * 4], stage_b + 3 * TILE_E * 2 + boff);
            }
            #pragma unroll
            for (int mf = 0; mf < 2; mf++)
                #pragma unroll
                for (int nf = 0; nf < 8; nf++) {
                    mma16816(d[mf][nf], ah[mf], &bh[nf * 2]);
                    mma16816(d[mf][nf], ah[mf], &bl[nf * 2]);
                    mma16816(d[mf][nf], al[mf], &bh[nf * 2]);
                }
        }
        __syncthreads();
    }

    // epilogue: bias + relu -> bf16 hi/lo stores + head row-norms
    auto st2 = [&](float a, float bb, int r, int c) {
        unsigned short ha, la, hb2, lb2;
        split1(a, ha, la);
        split1(bb, hb2, lb2);
        ushort2 hu; hu.x = ha; hu.y = hb2;
        ushort2 lu; lu.x = la; lu.y = lb2;
        *(ushort2*)(Ph + (size_t)r * UDIM + c) = hu;
        *(ushort2*)(Pl + (size_t)r * UDIM + c) = lu;
    };

    #pragma unroll
    for (int mf = 0; mf < 2; mf++) {
        int r0 = m0 + wm * 32 + mf * 16 + (lane >> 2);
        int r1 = r0 + 8;
        float ssA = 0.f, ssB = 0.f;
        #pragma unroll
        for (int nf = 0; nf < 8; nf++) {
            int col = n0 + wn * 64 + nf * 8 + (lane & 3) * 2;
            float2 bv2 = *(const float2*)(bias + col);
            float v0 = d[mf][nf][0] + bv2.x; v0 = v0 > 0.f ? v0 : 0.f;
            float v1 = d[mf][nf][1] + bv2.y; v1 = v1 > 0.f ? v1 : 0.f;
            float v2 = d[mf][nf][2] + bv2.x; v2 = v2 > 0.f ? v2 : 0.f;
            float v3 = d[mf][nf][3] + bv2.y; v3 = v3 > 0.f ? v3 : 0.f;
            st2(v0, v1, r0, col);
            st2(v2, v3, r1, col);
            ssA += v0 * v0 + v1 * v1;
            ssB += v2 * v2 + v3 * v3;
        }
        if (z < 2) {
            ssA += __shfl_xor_sync(0xffffffffu, ssA, 1);
            ssA += __shfl_xor_sync(0xffffffffu, ssA, 2);
            ssB += __shfl_xor_sync(0xffffffffu, ssB, 1);
            ssB += __shfl_xor_sync(0xffffffffu, ssB, 2);
            if ((lane & 3) == 0) {
                float* ndst = (z == 0) ? g_Qn : g_Kn;
                int h = blockIdx.y * 2 + wn;
                ndst[h * (BDIM * LSEQ) + r0] = ssA;
                ndst[h * (BDIM * LSEQ) + r1] = ssB;
            }
        }
    }
}

// ---------------- kernel 2: tensor-core attention ----------------
// Block = 64 q-rows x one hb, 128 thr = 4 warps, each warp 16 q x 64 k.
// QK^T and P.V on bf16 split-2 MMA; P stays in registers (C->A frag identity).
// smem (bf16 el): Qh[4096] Ql[4096] | K stages 2x(Kh+Kl)[8192] | V 2x[8192] | kn f32[2][64]
#define SQH 0
#define SQL 4096
#define SK0 8192
#define SV0 24576
#define ATT_SMEM_ELEMS 40960
#define ATT_SMEM_BYTES (ATT_SMEM_ELEMS * 2 + 512)   // 82432

__global__ __launch_bounds__(128)
void attn_mma(float* __restrict__ out, float* __restrict__ score_out) {
    extern __shared__ __nv_bfloat16 smb[];
    float* kn = (float*)(smb + ATT_SMEM_ELEMS);
    const int tid = threadIdx.x, lane = tid & 31, wid = tid >> 5;
    const int q0 = blockIdx.x * 64;
    const int hb = blockIdx.y, h = hb >> 2, b = hb & 3;
    const size_t XSZ = (size_t)BDIM * LSEQ * UDIM;
    const __nv_bfloat16* Qh_g = g_Ph;
    const __nv_bfloat16* Ql_g = g_Pl;
    const __nv_bfloat16* Kh_g = g_Ph + XSZ;
    const __nv_bfloat16* Kl_g = g_Pl + XSZ;
    const __nv_bfloat16* Vh_g = g_Ph + 2 * XSZ;
    const __nv_bfloat16* Vl_g = g_Pl + 2 * XSZ;

    auto load_tile = [&](const __nv_bfloat16* src, int row0, int dstoff) {
        #pragma unroll
        for (int i = 0; i < 4; i++) {
            int qid = tid + i * 128;
            int r = qid >> 3, c = qid & 7;
            cpa16(smb + dstoff + r * 64 + ((c ^ (r & 7)) << 3),
                  src + (size_t)(b * LSEQ + row0 + r) * UDIM + h * DDIM + c * 8);
        }
    };
    auto issue_stage = [&](int t) {
        int buf = t & 1;
        load_tile(Kh_g, t * 64, SK0 + buf * 8192);
        load_tile(Kl_g, t * 64, SK0 + buf * 8192 + 4096);
        load_tile(Vh_g, t * 64, SV0 + buf * 8192);
        load_tile(Vl_g, t * 64, SV0 + buf * 8192 + 4096);
        if (tid < 16) cpa16(kn + buf * 64 + tid * 4,
                            g_Kn + (size_t)h * (BDIM * LSEQ) + b * LSEQ + t * 64 + tid * 4);
        CPA_COMMIT();
    };

    load_tile(Qh_g, q0, SQH);
    load_tile(Ql_g, q0, SQL);
    issue_stage(0);          // group 0: Q + stage0 + kn0
    issue_stage(1);          // group 1

    const int rr = lane >> 2;
    const int qrow = q0 + wid * 16 + rr;
    float qq0 = g_Qn[(size_t)h * (BDIM * LSEQ) + b * LSEQ + qrow];
    float qq1 = g_Qn[(size_t)h * (BDIM * LSEQ) + b * LSEQ + qrow + 8];
    float qm0 = g_qm[b * LSEQ + qrow];
    float qm1 = g_qm[b * LSEQ + qrow + 8];

    CPA_WAIT(1);
    __syncthreads();

    // preload Q A-fragments (static across k-tiles)
    const uint32_t smem_u = (uint32_t)__cvta_generic_to_shared(smb);
    const int arow = wid * 16 + (lane & 15);
    const int asel = lane >> 4;
    uint32_t qhf[4][4], qlf[4][4];
    #pragma unroll
    for (int ks = 0; ks < 4; ks++) {
        uint32_t aoff = (uint32_t)(arow * 64 + (((ks * 2 + asel) ^ (lane & 7)) << 3)) * 2;
        ldsm4(qhf[ks], smem_u + SQH * 2 + aoff);
        ldsm4(qlf[ks], smem_u + SQL * 2 + aoff);
    }

    const int nrow = (lane & 7) + ((lane >> 4) << 3);       // K b-frag storage row
    const int nhalf = (lane >> 3) & 1;                      // K chunk half
    const int vkrow = (lane & 7) + (((lane >> 3) & 1) << 3);// V trans k-row
    const int vdsel = lane >> 4;                            // V d-chunk half

    float o[8][4];
    #pragma unroll
    for (int nf = 0; nf < 8; nf++)
        #pragma unroll
        for (int e = 0; e < 4; e++) o[nf][e] = 0.f;
    float l0 = 0.f, l1 = 0.f;
    const float C8 = 0.18033688f;    // log2(e)/8

    for (int t = 0; t < 8; t++) {
        const int buf = t & 1;
        const uint32_t kbh = smem_u + (SK0 + buf * 8192) * 2;
        const uint32_t kbl = kbh + 4096 * 2;
        const uint32_t vbh = smem_u + (SV0 + buf * 8192) * 2;
        const uint32_t vbl = vbh + 4096 * 2;

        // ---- S = Q.K^T (split-2: hh + hl + lh) ----
        float s[8][4];
        #pragma unroll
        for (int nf = 0; nf < 8; nf++)
            #pragma unroll
            for (int e = 0; e < 4; e++) s[nf][e] = 0.f;
        #pragma unroll
        for (int ks = 0; ks < 4; ks++) {
            uint32_t kh[4][4], kl[4][4];
            #pragma unroll
            for (int g = 0; g < 4; g++) {
                uint32_t off = (uint32_t)((g * 16 + nrow) * 64 +
                                          (((ks * 2 + nhalf) ^ (lane & 7)) << 3)) * 2;
                ldsm4(kh[g], kbh + off);
                ldsm4(kl[g], kbl + off);
            }
            #pragma unroll
            for (int nf = 0; nf < 8; nf++) {
                const uint32_t* bh = &kh[nf >> 1][(nf & 1) * 2];
                const uint32_t* bl = &kl[nf >> 1][(nf & 1) * 2];
                mma16816(s[nf], qhf[ks], bh);
                mma16816(s[nf], qhf[ks], bl);
                mma16816(s[nf], qlf[ks], bh);
            }
        }

        // ---- scores + exp + pack P (hi/lo) ----
        uint32_t pah[8][2], pal[8][2];
        #pragma unroll
        for (int nf = 0; nf < 8; nf++) {
            int c0 = nf * 8 + (lane & 3) * 2;
            float kk0 = kn[buf * 64 + c0];
            float kk1 = kn[buf * 64 + c0 + 1];
            float e0 = fmaxf(qq0 + kk0 - 2.f * s[nf][0], 1e-12f);
            float e1 = fmaxf(qq0 + kk1 - 2.f * s[nf][1], 1e-12f);
            float e2 = fmaxf(qq1 + kk0 - 2.f * s[nf][2], 1e-12f);
            float e3 = fmaxf(qq1 + kk1 - 2.f * s[nf][3], 1e-12f);
            float sq0 = sqrt_nm(e0), sq1 = sqrt_nm(e1);
            float sq2 = sqrt_nm(e2), sq3 = sqrt_nm(e3);
            size_t sr0 = ((size_t)(hb * LSEQ + qrow)) * LSEQ + t * 64 + c0;
            size_t sr1 = sr0 + (size_t)8 * LSEQ;
            *(float2*)(score_out + sr0) = make_float2(-0.125f * sq0 * qm0, -0.125f * sq1 * qm0);
            *(float2*)(score_out + sr1) = make_float2(-0.125f * sq2 * qm1, -0.125f * sq3 * qm1);
            float p0 = exp2_poly(-C8 * sq0);
            float p1 = exp2_poly(-C8 * sq1);
            float p2 = exp2_poly(-C8 * sq2);
            float p3 = exp2_poly(-C8 * sq3);
            l0 += p0 + p1; l1 += p2 + p3;
            uint32_t h01 = cvt_bf2(p0, p1);
            uint32_t h23 = cvt_bf2(p2, p3);
            pah[nf][0] = h01; pah[nf][1] = h23;
            float f0 = __uint_as_float(h01 << 16), f1 = __uint_as_float(h01 & 0xFFFF0000u);
            float f2 = __uint_as_float(h23 << 16), f3 = __uint_as_float(h23 & 0xFFFF0000u);
            pal[nf][0] = cvt_bf2(p0 - f0, p1 - f1);
            pal[nf][1] = cvt_bf2(p2 - f2, p3 - f3);
        }

        // ---- O += P.V (split-2) ----
        #pragma unroll
        for (int ks = 0; ks < 4; ks++) {
            uint32_t vh[4][4], vl[4][4];
            #pragma unroll
            for (int g = 0; g < 4; g++) {
                int row = ks * 16 + vkrow;
                uint32_t off = (uint32_t)(row * 64 + (((g * 2 + vdsel) ^ (lane & 7)) << 3)) * 2;
                ldsm4t(vh[g], vbh + off);
                ldsm4t(vl[g], vbl + off);
            }
            uint32_t Ah[4] = {pah[2 * ks][0], pah[2 * ks][1], pah[2 * ks + 1][0], pah[2 * ks + 1][1]};
            uint32_t Al[4] = {pal[2 * ks][0], pal[2 * ks][1], pal[2 * ks + 1][0], pal[2 * ks + 1][1]};
            #pragma unroll
            for (int nf = 0; nf < 8; nf++) {
                const uint32_t* bh = &vh[nf >> 1][(nf & 1) * 2];
                const uint32_t* bl = &vl[nf >> 1][(nf & 1) * 2];
                mma16816(o[nf], Ah, bh);
                mma16816(o[nf], Ah, bl);
                mma16816(o[nf], Al, bh);
            }
        }

        __syncthreads();     // all warps done with buf before overwrite
        if (t + 2 < 8)      { issue_stage(t + 2); CPA_WAIT(1); }
        else if (t < 7)     { CPA_WAIT(0); }
        if (t < 7) __syncthreads();   // stage t+1 visible
    }

    // l over 64 cols: quad butterfly
    l0 += __shfl_xor_sync(0xffffffffu, l0, 1);
    l0 += __shfl_xor_sync(0xffffffffu, l0, 2);
    l1 += __shfl_xor_sync(0xffffffffu, l1, 1);
    l1 += __shfl_xor_sync(0xffffffffu, l1, 2);
    float sc0 = qm0 / l0, sc1 = qm1 / l1;

    const int orow = b * LSEQ + qrow;
    #pragma unroll
    for (int nf = 0; nf < 8; nf++) {
        int col = h * DDIM + nf * 8 + (lane & 3) * 2;
        *(float2*)(out + (size_t)orow * UDIM + col) =
            make_float2(o[nf][0] * sc0, o[nf][1] * sc0);
        *(float2*)(out + (size_t)(orow + 8) * UDIM + col) =
            make_float2(o[nf][2] * sc1, o[nf][3] * sc1);
    }
}

// ---------------- launcher ----------------
extern "C" void kernel_launch(void* const* d_in, const int* in_sizes, int n_in,
                              void* d_out, int out_size) {
    (void)in_sizes; (void)n_in; (void)out_size;
    const float* queries = (const float*)d_in[0];
    const float* keys    = (const float*)d_in[1];
    const float* values  = (const float*)d_in[2];
    const float* Wq = (const float*)d_in[3];
    const float* bq = (const float*)d_in[4];
    const float* Wk = (const float*)d_in[5];
    const float* bk = (const float*)d_in[6];
    const float* Wv = (const float*)d_in[7];
    const float* bv = (const float*)d_in[8];

    float* out_ptr   = (float*)d_out;
    float* score_ptr = out_ptr + (size_t)BDIM * LSEQ * UDIM;

    cudaFuncSetAttribute(qkv_gemm_mma, cudaFuncAttributeMaxDynamicSharedMemorySize,
                         GEMM_SMEM_BYTES);
    cudaFuncSetAttribute(attn_mma, cudaFuncAttributeMaxDynamicSharedMemorySize,
                         ATT_SMEM_BYTES);

    dim3 sxgrid((BDIM * LSEQ * UDIM) / (256 * 4), 3);
    split_x_kernel<<<sxgrid, 256>>>(queries, keys, values);
    dim3 swgrid(UDIM / 32, UDIM / 32, 3);
    split_w_kernel<<<swgrid, 256>>>(Wq, Wk, Wv);

    dim3 ggrid(BDIM * LSEQ / 128, UDIM / 128, 3);
    qkv_gemm_mma<<<ggrid, 256, GEMM_SMEM_BYTES>>>(bq, bk, bv);

    dim3 agrid(LSEQ / 64, HBDIM);
    attn_mma<<<agrid, 128, ATT_SMEM_BYTES>>>(out_ptr, score_ptr);
}

// round 13
// speedup vs baseline: 3.2192x; 1.1155x over previous
#include <cuda_runtime.h>
#include <cuda_bf16.h>
#include <cstdint>

#define LSEQ 512
#define UDIM 512
#define BDIM 4
#define HDIM 8
#define DDIM 64
#define HBDIM 32

// ---------------- scratch (device globals, no allocation) ----------------
__device__ float g_qm[BDIM * LSEQ];
__device__ float g_Qn[HDIM * BDIM * LSEQ];
__device__ float g_Kn[HDIM * BDIM * LSEQ];
__device__ float g_Wt[3 * UDIM * UDIM];               // W^T, tf32-rounded fp32
__device__ __nv_bfloat16 g_Ph[3 * BDIM * LSEQ * UDIM];  // projected Q/K/V hi
__device__ __nv_bfloat16 g_Pl[3 * BDIM * LSEQ * UDIM];  // projected Q/K/V lo
__device__ float g_Opart[2 * HBDIM * LSEQ * DDIM];    // kv-split partial O (8MB)
__device__ float g_lpart[2 * HBDIM * LSEQ];

// ---------------- helpers ----------------
__device__ __forceinline__ float sqrt_nm(float x) {
    float r = __int_as_float(0x5f3759df - (__float_as_int(x) >> 1));
    r = r * (1.5f - 0.5f * x * r * r);
    r = r * (1.5f - 0.5f * x * r * r);
    return x * r;
}
__device__ __forceinline__ float exp2_poly(float y) {
    y = fmaxf(y, -120.f);
    float fn = y + 12582912.f;
    int ib = __float_as_int(fn);
    float n = fn - 12582912.f;
    float f = y - n;
    float scale = __int_as_float((ib - 0x4B400000 + 127) << 23);
    float p = 0.0013333558f;
    p = fmaf(p, f, 0.0096181291f);
    p = fmaf(p, f, 0.0555041087f);
    p = fmaf(p, f, 0.2402265069f);
    p = fmaf(p, f, 0.6931471806f);
    p = fmaf(p, f, 1.0f);
    return scale * p;
}
__device__ __forceinline__ void cpa16(void* sdst, const void* gsrc) {
    uint32_t s = (uint32_t)__cvta_generic_to_shared(sdst);
    asm volatile("cp.async.cg.shared.global [%0], [%1], 16;" :: "r"(s), "l"(gsrc));
}
#define CPA_COMMIT() asm volatile("cp.async.commit_group;")
#define CPA_WAIT(n)  asm volatile("cp.async.wait_group %0;" :: "n"(n))

__device__ __forceinline__ void ldsm4(uint32_t* r, uint32_t addr) {
    asm volatile("ldmatrix.sync.aligned.m8n8.x4.shared.b16 {%0,%1,%2,%3}, [%4];"
                 : "=r"(r[0]), "=r"(r[1]), "=r"(r[2]), "=r"(r[3]) : "r"(addr));
}
__device__ __forceinline__ void ldsm4t(uint32_t* r, uint32_t addr) {
    asm volatile("ldmatrix.sync.aligned.m8n8.x4.trans.shared.b16 {%0,%1,%2,%3}, [%4];"
                 : "=r"(r[0]), "=r"(r[1]), "=r"(r[2]), "=r"(r[3]) : "r"(addr));
}
__device__ __forceinline__ void mma16816(float* d, const uint32_t* a, const uint32_t* b) {
    asm volatile(
        "mma.sync.aligned.m16n8k16.row.col.f32.bf16.bf16.f32 "
        "{%0,%1,%2,%3}, {%4,%5,%6,%7}, {%8,%9}, {%0,%1,%2,%3};"
        : "+f"(d[0]), "+f"(d[1]), "+f"(d[2]), "+f"(d[3])
        : "r"(a[0]), "r"(a[1]), "r"(a[2]), "r"(a[3]), "r"(b[0]), "r"(b[1]));
}
__device__ __forceinline__ void mma_tf32(float* d, const uint32_t* a, const uint32_t* b) {
    asm volatile(
        "mma.sync.aligned.m16n8k8.row.col.f32.tf32.tf32.f32 "
        "{%0,%1,%2,%3}, {%4,%5,%6,%7}, {%8,%9}, {%0,%1,%2,%3};"
        : "+f"(d[0]), "+f"(d[1]), "+f"(d[2]), "+f"(d[3])
        : "r"(a[0]), "r"(a[1]), "r"(a[2]), "r"(a[3]), "r"(b[0]), "r"(b[1]));
}
// tf32 round: b32 dst, f32 src (legal cvt form)
__device__ __forceinline__ uint32_t cvt_tf32(float x) {
    uint32_t d; asm("cvt.rna.tf32.f32 %0, %1;" : "=r"(d) : "f"(x)); return d;
}
__device__ __forceinline__ void cvt_tf32_4(uint32_t* r) {
    r[0] = cvt_tf32(__uint_as_float(r[0]));
    r[1] = cvt_tf32(__uint_as_float(r[1]));
    r[2] = cvt_tf32(__uint_as_float(r[2]));
    r[3] = cvt_tf32(__uint_as_float(r[3]));
}
__device__ __forceinline__ uint32_t cvt_bf2(float lo, float hi) {
    uint32_t d; asm("cvt.rn.bf16x2.f32 %0, %1, %2;" : "=r"(d) : "f"(hi), "f"(lo)); return d;
}
__device__ __forceinline__ unsigned short bfbits(__nv_bfloat16 h) {
    return *reinterpret_cast<unsigned short*>(&h);
}
__device__ __forceinline__ void split1(float x, unsigned short& h, unsigned short& l) {
    __nv_bfloat16 hb = __float2bfloat16_rn(x);
    float lf = x - __bfloat162float(hb);
    __nv_bfloat16 lb = __float2bfloat16_rn(lf);
    h = bfbits(hb); l = bfbits(lb);
}

// ---------------- kernel A: transpose W -> [n][k] fp32, tf32-rounded ------
__global__ void transpose_w_kernel(const float* __restrict__ Wq,
                                   const float* __restrict__ Wk,
                                   const float* __restrict__ Wv) {
    __shared__ float t[32][33];
    int z = blockIdx.z;
    const float* W = (z == 0) ? Wq : (z == 1) ? Wk : Wv;
    float* D = g_Wt + (size_t)z * UDIM * UDIM;
    int k0 = blockIdx.x * 32;
    int n0 = blockIdx.y * 32;
    int tx = threadIdx.x & 31, ty = threadIdx.x >> 5;
    #pragma unroll
    for (int i = 0; i < 4; i++) {
        int r = ty + i * 8;
        t[r][tx] = W[(size_t)(k0 + r) * UDIM + n0 + tx];
    }
    __syncthreads();
    #pragma unroll
    for (int i = 0; i < 4; i++) {
        int r = ty + i * 8;
        uint32_t v = cvt_tf32(t[tx][r]);
        D[(size_t)(n0 + r) * UDIM + k0 + tx] = __uint_as_float(v);
    }
}

// ---------------- kernel B: query mask ----------------
__global__ void qm_kernel(const float* __restrict__ q_in) {
    __shared__ float rs[8];
    size_t i = ((size_t)blockIdx.x * 256 + threadIdx.x) * 4;
    float4 x = *(const float4*)(q_in + i);
    float s = x.x + x.y + x.z + x.w;
    #pragma unroll
    for (int o = 16; o; o >>= 1) s += __shfl_xor_sync(0xffffffffu, s, o);
    if ((threadIdx.x & 31) == 0) rs[threadIdx.x >> 5] = s;
    __syncthreads();
    if ((threadIdx.x & 127) == 0) {
        int w0 = threadIdx.x >> 5;
        float t = rs[w0] + rs[w0 + 1] + rs[w0 + 2] + rs[w0 + 3];
        g_qm[i >> 9] = (t != 0.f) ? 1.f : 0.f;
    }
}

// ---------------- kernel 1: tf32 tensor-core GEMM ----------------
// relu(X@W+b) -> bf16 hi/lo + head row-norms. M=128, N=128, kc=32 fp32.
// 256 thr = 8 warps (4m x 2n), warp 32x64. XOR-swizzled fp32 smem.
#define GSTAGE_F 8192                         // X 128x32 + W 128x32 floats
#define GEMM_SMEM_BYTES (2 * GSTAGE_F * 4)    // 65536

__global__ __launch_bounds__(256)
void qkv_gemm_tf32(const float* __restrict__ q_in,
                   const float* __restrict__ k_in,
                   const float* __restrict__ v_in,
                   const float* __restrict__ bq,
                   const float* __restrict__ bk,
                   const float* __restrict__ bv) {
    extern __shared__ float gsm[];
    const int z = blockIdx.z;
    const size_t XSZ = (size_t)BDIM * LSEQ * UDIM;
    const float* X = (z == 0) ? q_in : (z == 1) ? k_in : v_in;
    const float* Wt = g_Wt + (size_t)z * UDIM * UDIM;
    const float* bias = (z == 0) ? bq : (z == 1) ? bk : bv;
    __nv_bfloat16* Ph = g_Ph + z * XSZ;
    __nv_bfloat16* Pl = g_Pl + z * XSZ;

    const int tid = threadIdx.x;
    const int wid = tid >> 5;
    const int lane = tid & 31;
    const int wm = wid & 3;
    const int wn = wid >> 2;
    const int m0 = blockIdx.x * 128;
    const int n0 = blockIdx.y * 128;

    auto issue = [&](int kc, int buf) {
        float* st = gsm + buf * GSTAGE_F;
        #pragma unroll
        for (int i = 0; i < 4; i++) {                 // X: 128x8 chunks
            int q = tid + i * 256;
            int r = q >> 3, c = q & 7;
            cpa16(st + r * 32 + ((c ^ (r & 7)) << 2),
                  X + (size_t)(m0 + r) * UDIM + kc * 32 + c * 4);
        }
        #pragma unroll
        for (int i = 0; i < 4; i++) {                 // W: 128x8 chunks
            int q = tid + i * 256;
            int r = q >> 3, c = q & 7;
            cpa16(st + 4096 + r * 32 + ((c ^ (r & 7)) << 2),
                  Wt + (size_t)(n0 + r) * UDIM + kc * 32 + c * 4);
        }
        CPA_COMMIT();
    };

    float d[2][8][4];
    #pragma unroll
    for (int mf = 0; mf < 2; mf++)
        #pragma unroll
        for (int nf = 0; nf < 8; nf++)
            #pragma unroll
            for (int e = 0; e < 4; e++) d[mf][nf][e] = 0.f;

    const uint32_t smem_u = (uint32_t)__cvta_generic_to_shared(gsm);
    const int arow = wm * 32 + (lane & 15);           // + mf*16
    const int aseL = lane >> 4;
    const int brow = wn * 64 + (lane & 7) + ((lane >> 4) << 3);  // + ng*16
    const int bseL = (lane >> 3) & 1;

    issue(0, 0);

    for (int kc = 0; kc < 16; kc++) {
        if (kc < 15) { issue(kc + 1, (kc + 1) & 1); CPA_WAIT(1); }
        else         { CPA_WAIT(0); }
        __syncthreads();

        const uint32_t stage_b = smem_u + ((kc & 1) ? GSTAGE_F * 4 : 0);

        #pragma unroll
        for (int s = 0; s < 4; s++) {
            uint32_t a[2][4];
            #pragma unroll
            for (int mf = 0; mf < 2; mf++) {
                int row = arow + mf * 16;
                uint32_t off = (uint32_t)(row * 32 + (((2 * s + aseL) ^ (row & 7)) << 2)) * 4;
                ldsm4(a[mf], stage_b + off);
                cvt_tf32_4(a[mf]);
            }
            uint32_t bfr[4][4];
            #pragma unroll
            for (int ng = 0; ng < 4; ng++) {
                int row = brow + ng * 16;
                uint32_t off = (uint32_t)(4096 * 4) +
                               (uint32_t)(row * 32 + (((2 * s + bseL) ^ (row & 7)) << 2)) * 4;
                ldsm4(bfr[ng], stage_b + off);
            }
            #pragma unroll
            for (int nf = 0; nf < 8; nf++) {
                const uint32_t* bp = &bfr[nf >> 1][(nf & 1) * 2];
                mma_tf32(d[0][nf], a[0], bp);
                mma_tf32(d[1][nf], a[1], bp);
            }
        }
        __syncthreads();
    }

    // epilogue: bias + relu -> bf16 hi/lo + head norms
    auto st2 = [&](float a, float bb, int r, int c) {
        unsigned short ha, la, hb2, lb2;
        split1(a, ha, la);
        split1(bb, hb2, lb2);
        ushort2 hu; hu.x = ha; hu.y = hb2;
        ushort2 lu; lu.x = la; lu.y = lb2;
        *(ushort2*)(Ph + (size_t)r * UDIM + c) = hu;
        *(ushort2*)(Pl + (size_t)r * UDIM + c) = lu;
    };

    #pragma unroll
    for (int mf = 0; mf < 2; mf++) {
        int r0 = m0 + wm * 32 + mf * 16 + (lane >> 2);
        int r1 = r0 + 8;
        float ssA = 0.f, ssB = 0.f;
        #pragma unroll
        for (int nf = 0; nf < 8; nf++) {
            int col = n0 + wn * 64 + nf * 8 + (lane & 3) * 2;
            float2 bv2 = *(const float2*)(bias + col);
            float v0 = d[mf][nf][0] + bv2.x; v0 = v0 > 0.f ? v0 : 0.f;
            float v1 = d[mf][nf][1] + bv2.y; v1 = v1 > 0.f ? v1 : 0.f;
            float v2 = d[mf][nf][2] + bv2.x; v2 = v2 > 0.f ? v2 : 0.f;
            float v3 = d[mf][nf][3] + bv2.y; v3 = v3 > 0.f ? v3 : 0.f;
            st2(v0, v1, r0, col);
            st2(v2, v3, r1, col);
            ssA += v0 * v0 + v1 * v1;
            ssB += v2 * v2 + v3 * v3;
        }
        if (z < 2) {
            ssA += __shfl_xor_sync(0xffffffffu, ssA, 1);
            ssA += __shfl_xor_sync(0xffffffffu, ssA, 2);
            ssB += __shfl_xor_sync(0xffffffffu, ssB, 1);
            ssB += __shfl_xor_sync(0xffffffffu, ssB, 2);
            if ((lane & 3) == 0) {
                float* ndst = (z == 0) ? g_Qn : g_Kn;
                int h = blockIdx.y * 2 + wn;
                ndst[h * (BDIM * LSEQ) + r0] = ssA;
                ndst[h * (BDIM * LSEQ) + r1] = ssB;
            }
        }
    }
}

// ---------------- kernel 2: tensor-core attention, kv-split x2 ------------
// Block = 64 q x one hb x half-K (4 tiles), 128 thr = 4 warps x 16q x 64k.
// K double-buffered, V single-buffered (load hides under S). Partial O/l out.
// smem (bf16 el): Qh 0 | Ql 4096 | K 2x(hi,lo) 8192.. | V (hi,lo) 24576.. | kn
#define AT_SMEM_ELEMS 32768
#define AT_SMEM_BYTES (AT_SMEM_ELEMS * 2 + 512)   // 66048

__global__ __launch_bounds__(128)
void attn_mma(float* __restrict__ score_out) {
    extern __shared__ __nv_bfloat16 smb[];
    float* kn = (float*)(smb + AT_SMEM_ELEMS);
    const int tid = threadIdx.x, lane = tid & 31, wid = tid >> 5;
    const int q0 = blockIdx.x * 64;
    const int hb = blockIdx.y, h = hb >> 2, b = hb & 3;
    const int z = blockIdx.z;
    const size_t XSZ = (size_t)BDIM * LSEQ * UDIM;
    const __nv_bfloat16* Qh_g = g_Ph;
    const __nv_bfloat16* Ql_g = g_Pl;
    const __nv_bfloat16* Kh_g = g_Ph + XSZ;
    const __nv_bfloat16* Kl_g = g_Pl + XSZ;
    const __nv_bfloat16* Vh_g = g_Ph + 2 * XSZ;
    const __nv_bfloat16* Vl_g = g_Pl + 2 * XSZ;

    auto load_tile = [&](const __nv_bfloat16* src, int row0, int dstoff) {
        #pragma unroll
        for (int i = 0; i < 4; i++) {
            int qid = tid + i * 128;
            int r = qid >> 3, c = qid & 7;
            cpa16(smb + dstoff + r * 64 + ((c ^ (r & 7)) << 3),
                  src + (size_t)(b * LSEQ + row0 + r) * UDIM + h * DDIM + c * 8);
        }
    };
    auto issue_K = [&](int tl) {
        int row0 = (z * 4 + tl) * 64;
        load_tile(Kh_g, row0, 8192 + (tl & 1) * 8192);
        load_tile(Kl_g, row0, 8192 + (tl & 1) * 8192 + 4096);
        if (tid < 16) cpa16(kn + (tl & 1) * 64 + tid * 4,
                            g_Kn + (size_t)h * (BDIM * LSEQ) + b * LSEQ + row0 + tid * 4);
    };
    auto issue_V = [&](int tl) {
        int row0 = (z * 4 + tl) * 64;
        load_tile(Vh_g, row0, 24576);
        load_tile(Vl_g, row0, 28672);
    };

    // G0: Q + K0 + kn0
    load_tile(Qh_g, q0, 0);
    load_tile(Ql_g, q0, 4096);
    issue_K(0);
    CPA_COMMIT();

    const int rr = lane >> 2;
    const int qrow = q0 + wid * 16 + rr;
    float qq0 = g_Qn[(size_t)h * (BDIM * LSEQ) + b * LSEQ + qrow];
    float qq1 = g_Qn[(size_t)h * (BDIM * LSEQ) + b * LSEQ + qrow + 8];
    float qm0 = g_qm[b * LSEQ + qrow];
    float qm1 = g_qm[b * LSEQ + qrow + 8];

    const uint32_t smem_u = (uint32_t)__cvta_generic_to_shared(smb);
    const int arow = wid * 16 + (lane & 15);
    const int asel = lane >> 4;
    const int nrow = (lane & 7) + ((lane >> 4) << 3);
    const int nhalf = (lane >> 3) & 1;
    const int vkrow = (lane & 7) + (((lane >> 3) & 1) << 3);
    const int vdsel = lane >> 4;

    uint32_t qhf[4][4], qlf[4][4];
    float o[8][4];
    #pragma unroll
    for (int nf = 0; nf < 8; nf++)
        #pragma unroll
        for (int e = 0; e < 4; e++) o[nf][e] = 0.f;
    float l0 = 0.f, l1 = 0.f;
    const float C8 = 0.18033688f;

    for (int t = 0; t < 4; t++) {
        issue_V(t);
        CPA_COMMIT();
        if (t < 3) issue_K(t + 1);
        CPA_COMMIT();
        CPA_WAIT(2);            // K_t (and Q at t=0) complete
        __syncthreads();

        if (t == 0) {
            #pragma unroll
            for (int ks = 0; ks < 4; ks++) {
                uint32_t aoff = (uint32_t)(arow * 64 + (((ks * 2 + asel) ^ (lane & 7)) << 3)) * 2;
                ldsm4(qhf[ks], smem_u + aoff);
                ldsm4(qlf[ks], smem_u + 4096 * 2 + aoff);
            }
        }

        const uint32_t kbh = smem_u + (8192 + (t & 1) * 8192) * 2;
        const uint32_t kbl = kbh + 4096 * 2;

        // ---- S = Q.K^T (bf16 split-2) ----
        float s[8][4];
        #pragma unroll
        for (int nf = 0; nf < 8; nf++)
            #pragma unroll
            for (int e = 0; e < 4; e++) s[nf][e] = 0.f;
        #pragma unroll
        for (int ks = 0; ks < 4; ks++) {
            uint32_t kh[4][4], kl[4][4];
            #pragma unroll
            for (int g = 0; g < 4; g++) {
                uint32_t off = (uint32_t)((g * 16 + nrow) * 64 +
                                          (((ks * 2 + nhalf) ^ (lane & 7)) << 3)) * 2;
                ldsm4(kh[g], kbh + off);
                ldsm4(kl[g], kbl + off);
            }
            #pragma unroll
            for (int nf = 0; nf < 8; nf++) {
                const uint32_t* bh = &kh[nf >> 1][(nf & 1) * 2];
                const uint32_t* bl = &kl[nf >> 1][(nf & 1) * 2];
                mma16816(s[nf], qhf[ks], bh);
                mma16816(s[nf], qhf[ks], bl);
                mma16816(s[nf], qlf[ks], bh);
            }
        }

        // ---- scores + exp + pack P ----
        uint32_t pah[8][2], pal[8][2];
        #pragma unroll
        for (int nf = 0; nf < 8; nf++) {
            int c0 = nf * 8 + (lane & 3) * 2;
            float kk0 = kn[(t & 1) * 64 + c0];
            float kk1 = kn[(t & 1) * 64 + c0 + 1];
            float e0 = fmaxf(qq0 + kk0 - 2.f * s[nf][0], 1e-12f);
            float e1 = fmaxf(qq0 + kk1 - 2.f * s[nf][1], 1e-12f);
            float e2 = fmaxf(qq1 + kk0 - 2.f * s[nf][2], 1e-12f);
            float e3 = fmaxf(qq1 + kk1 - 2.f * s[nf][3], 1e-12f);
            float sq0 = sqrt_nm(e0), sq1 = sqrt_nm(e1);
            float sq2 = sqrt_nm(e2), sq3 = sqrt_nm(e3);
            size_t sr0 = ((size_t)(hb * LSEQ + qrow)) * LSEQ + (z * 4 + t) * 64 + c0;
            size_t sr1 = sr0 + (size_t)8 * LSEQ;
            *(float2*)(score_out + sr0) = make_float2(-0.125f * sq0 * qm0, -0.125f * sq1 * qm0);
            *(float2*)(score_out + sr1) = make_float2(-0.125f * sq2 * qm1, -0.125f * sq3 * qm1);
            float p0 = exp2_poly(-C8 * sq0);
            float p1 = exp2_poly(-C8 * sq1);
            float p2 = exp2_poly(-C8 * sq2);
            float p3 = exp2_poly(-C8 * sq3);
            l0 += p0 + p1; l1 += p2 + p3;
            uint32_t h01 = cvt_bf2(p0, p1);
            uint32_t h23 = cvt_bf2(p2, p3);
            pah[nf][0] = h01; pah[nf][1] = h23;
            float f0 = __uint_as_float(h01 << 16), f1 = __uint_as_float(h01 & 0xFFFF0000u);
            float f2 = __uint_as_float(h23 << 16), f3 = __uint_as_float(h23 & 0xFFFF0000u);
            pal[nf][0] = cvt_bf2(p0 - f0, p1 - f1);
            pal[nf][1] = cvt_bf2(p2 - f2, p3 - f3);
        }

        CPA_WAIT(1);            // V_t complete (K_{t+1} may be in flight)
        __syncthreads();

        // ---- O += P.V (bf16 split-2) ----
        const uint32_t vbh = smem_u + 24576 * 2;
        const uint32_t vbl = smem_u + 28672 * 2;
        #pragma unroll
        for (int ks = 0; ks < 4; ks++) {
            uint32_t vh[4][4], vl[4][4];
            #pragma unroll
            for (int g = 0; g < 4; g++) {
                int row = ks * 16 + vkrow;
                uint32_t off = (uint32_t)(row * 64 + (((g * 2 + vdsel) ^ (lane & 7)) << 3)) * 2;
                ldsm4t(vh[g], vbh + off);
                ldsm4t(vl[g], vbl + off);
            }
            uint32_t Ah[4] = {pah[2 * ks][0], pah[2 * ks][1], pah[2 * ks + 1][0], pah[2 * ks + 1][1]};
            uint32_t Al[4] = {pal[2 * ks][0], pal[2 * ks][1], pal[2 * ks + 1][0], pal[2 * ks + 1][1]};
            #pragma unroll
            for (int nf = 0; nf < 8; nf++) {
                const uint32_t* bh = &vh[nf >> 1][(nf & 1) * 2];
                const uint32_t* bl = &vl[nf >> 1][(nf & 1) * 2];
                mma16816(o[nf], Ah, bh);
                mma16816(o[nf], Ah, bl);
                mma16816(o[nf], Al, bh);
            }
        }
        __syncthreads();        // V buf & K buf free for next iteration
    }

    // partial l over 64 cols (quad butterfly), write partial O/l
    l0 += __shfl_xor_sync(0xffffffffu, l0, 1);
    l0 += __shfl_xor_sync(0xffffffffu, l0, 2);
    l1 += __shfl_xor_sync(0xffffffffu, l1, 1);
    l1 += __shfl_xor_sync(0xffffffffu, l1, 2);

    size_t prow = (size_t)(z * HBDIM + hb) * LSEQ + qrow;
    #pragma unroll
    for (int nf = 0; nf < 8; nf++) {
        int col = nf * 8 + (lane & 3) * 2;
        *(float2*)(g_Opart + prow * DDIM + col) = make_float2(o[nf][0], o[nf][1]);
        *(float2*)(g_Opart + (prow + 8) * DDIM + col) = make_float2(o[nf][2], o[nf][3]);
    }
    if ((lane & 3) == 0) {
        g_lpart[prow] = l0;
        g_lpart[prow + 8] = l1;
    }
}

// ---------------- kernel 3: combine kv-split halves ----------------
__global__ void combine_kernel(float* __restrict__ out) {
    int g = blockIdx.x * 256 + threadIdx.x;          // per float2
    int d = (g & 31) * 2;
    int row = g >> 5;                                 // hb*LSEQ + q
    float2 a = *(float2*)(g_Opart + (size_t)row * DDIM + d);
    float2 c = *(float2*)(g_Opart + ((size_t)(HBDIM * LSEQ) + row) * DDIM + d);
    float l = g_lpart[row] + g_lpart[HBDIM * LSEQ + row];
    int hb = row >> 9, q = row & 511;
    int h = hb >> 2, b = hb & 3;
    float s = g_qm[b * LSEQ + q] / l;
    *(float2*)(out + ((size_t)(b * LSEQ + q)) * UDIM + h * DDIM + d) =
        make_float2((a.x + c.x) * s, (a.y + c.y) * s);
}

// ---------------- launcher ----------------
extern "C" void kernel_launch(void* const* d_in, const int* in_sizes, int n_in,
                              void* d_out, int out_size) {
    (void)in_sizes; (void)n_in; (void)out_size;
    const float* queries = (const float*)d_in[0];
    const float* keys    = (const float*)d_in[1];
    const float* values  = (const float*)d_in[2];
    const float* Wq = (const float*)d_in[3];
    const float* bq = (const float*)d_in[4];
    const float* Wk = (const float*)d_in[5];
    const float* bk = (const float*)d_in[6];
    const float* Wv = (const float*)d_in[7];
    const float* bv = (const float*)d_in[8];

    float* out_ptr   = (float*)d_out;
    float* score_ptr = out_ptr + (size_t)BDIM * LSEQ * UDIM;

    cudaFuncSetAttribute(qkv_gemm_tf32, cudaFuncAttributeMaxDynamicSharedMemorySize,
                         GEMM_SMEM_BYTES);
    cudaFuncSetAttribute(attn_mma, cudaFuncAttributeMaxDynamicSharedMemorySize,
                         AT_SMEM_BYTES);

    dim3 twgrid(UDIM / 32, UDIM / 32, 3);
    transpose_w_kernel<<<twgrid, 256>>>(Wq, Wk, Wv);

    qm_kernel<<<(BDIM * LSEQ * UDIM) / (256 * 4), 256>>>(queries);

    dim3 ggrid(BDIM * LSEQ / 128, UDIM / 128, 3);
    qkv_gemm_tf32<<<ggrid, 256, GEMM_SMEM_BYTES>>>(queries, keys, values, bq, bk, bv);

    dim3 agrid(LSEQ / 64, HBDIM, 2);
    attn_mma<<<agrid, 128, AT_SMEM_BYTES>>>(score_ptr);

    combine_kernel<<<(HBDIM * LSEQ * DDIM / 2) / 256, 256>>>(out_ptr);
}

// round 14
// speedup vs baseline: 3.9962x; 1.2414x over previous
#include <cuda_runtime.h>
#include <cuda_fp16.h>
#include <cstdint>

#define LSEQ 512
#define UDIM 512
#define BDIM 4
#define HDIM 8
#define DDIM 64
#define HBDIM 32

// ---------------- scratch (device globals, no allocation) ----------------
__device__ float g_qm[BDIM * LSEQ];
__device__ float g_Qn[HDIM * BDIM * LSEQ];
__device__ float g_Kn[HDIM * BDIM * LSEQ];
__device__ float g_Wt[3 * UDIM * UDIM];               // W^T, tf32-rounded fp32
__device__ __half g_Pf[3 * BDIM * LSEQ * UDIM];       // projected Q/K/V, fp16
__device__ float g_Opart[2 * HBDIM * LSEQ * DDIM];    // kv-split partial O
__device__ float g_lpart[2 * HBDIM * LSEQ];

// ---------------- helpers ----------------
__device__ __forceinline__ float sqrt_nm(float x) {
    float r = __int_as_float(0x5f3759df - (__float_as_int(x) >> 1));
    r = r * (1.5f - 0.5f * x * r * r);
    r = r * (1.5f - 0.5f * x * r * r);
    return x * r;
}
__device__ __forceinline__ float exp2_poly(float y) {
    y = fmaxf(y, -120.f);
    float fn = y + 12582912.f;
    int ib = __float_as_int(fn);
    float n = fn - 12582912.f;
    float f = y - n;
    float scale = __int_as_float((ib - 0x4B400000 + 127) << 23);
    float p = 0.0013333558f;
    p = fmaf(p, f, 0.0096181291f);
    p = fmaf(p, f, 0.0555041087f);
    p = fmaf(p, f, 0.2402265069f);
    p = fmaf(p, f, 0.6931471806f);
    p = fmaf(p, f, 1.0f);
    return scale * p;
}
__device__ __forceinline__ void cpa16(void* sdst, const void* gsrc) {
    uint32_t s = (uint32_t)__cvta_generic_to_shared(sdst);
    asm volatile("cp.async.cg.shared.global [%0], [%1], 16;" :: "r"(s), "l"(gsrc));
}
#define CPA_COMMIT() asm volatile("cp.async.commit_group;")
#define CPA_WAIT(n)  asm volatile("cp.async.wait_group %0;" :: "n"(n))

__device__ __forceinline__ void ldsm4(uint32_t* r, uint32_t addr) {
    asm volatile("ldmatrix.sync.aligned.m8n8.x4.shared.b16 {%0,%1,%2,%3}, [%4];"
                 : "=r"(r[0]), "=r"(r[1]), "=r"(r[2]), "=r"(r[3]) : "r"(addr));
}
__device__ __forceinline__ void ldsm4t(uint32_t* r, uint32_t addr) {
    asm volatile("ldmatrix.sync.aligned.m8n8.x4.trans.shared.b16 {%0,%1,%2,%3}, [%4];"
                 : "=r"(r[0]), "=r"(r[1]), "=r"(r[2]), "=r"(r[3]) : "r"(addr));
}
__device__ __forceinline__ void mma_f16(float* d, const uint32_t* a, const uint32_t* b) {
    asm volatile(
        "mma.sync.aligned.m16n8k16.row.col.f32.f16.f16.f32 "
        "{%0,%1,%2,%3}, {%4,%5,%6,%7}, {%8,%9}, {%0,%1,%2,%3};"
        : "+f"(d[0]), "+f"(d[1]), "+f"(d[2]), "+f"(d[3])
        : "r"(a[0]), "r"(a[1]), "r"(a[2]), "r"(a[3]), "r"(b[0]), "r"(b[1]));
}
__device__ __forceinline__ void mma_tf32(float* d, const uint32_t* a, const uint32_t* b) {
    asm volatile(
        "mma.sync.aligned.m16n8k8.row.col.f32.tf32.tf32.f32 "
        "{%0,%1,%2,%3}, {%4,%5,%6,%7}, {%8,%9}, {%0,%1,%2,%3};"
        : "+f"(d[0]), "+f"(d[1]), "+f"(d[2]), "+f"(d[3])
        : "r"(a[0]), "r"(a[1]), "r"(a[2]), "r"(a[3]), "r"(b[0]), "r"(b[1]));
}
__device__ __forceinline__ uint32_t cvt_tf32(float x) {
    uint32_t d; asm("cvt.rna.tf32.f32 %0, %1;" : "=r"(d) : "f"(x)); return d;
}
__device__ __forceinline__ void cvt_tf32_4(uint32_t* r) {
    r[0] = cvt_tf32(__uint_as_float(r[0]));
    r[1] = cvt_tf32(__uint_as_float(r[1]));
    r[2] = cvt_tf32(__uint_as_float(r[2]));
    r[3] = cvt_tf32(__uint_as_float(r[3]));
}
__device__ __forceinline__ uint32_t packh2(float lo, float hi) {
    __half2 h = __floats2half2_rn(lo, hi);
    return *reinterpret_cast<uint32_t*>(&h);
}

// ---------------- kernel A: transpose W -> [n][k] fp32, tf32-rounded ------
__global__ void transpose_w_kernel(const float* __restrict__ Wq,
                                   const float* __restrict__ Wk,
                                   const float* __restrict__ Wv) {
    __shared__ float t[32][33];
    int z = blockIdx.z;
    const float* W = (z == 0) ? Wq : (z == 1) ? Wk : Wv;
    float* D = g_Wt + (size_t)z * UDIM * UDIM;
    int k0 = blockIdx.x * 32;
    int n0 = blockIdx.y * 32;
    int tx = threadIdx.x & 31, ty = threadIdx.x >> 5;
    #pragma unroll
    for (int i = 0; i < 4; i++) {
        int r = ty + i * 8;
        t[r][tx] = W[(size_t)(k0 + r) * UDIM + n0 + tx];
    }
    __syncthreads();
    #pragma unroll
    for (int i = 0; i < 4; i++) {
        int r = ty + i * 8;
        uint32_t v = cvt_tf32(t[tx][r]);
        D[(size_t)(n0 + r) * UDIM + k0 + tx] = __uint_as_float(v);
    }
}

// ---------------- kernel B: query mask ----------------
__global__ void qm_kernel(const float* __restrict__ q_in) {
    __shared__ float rs[8];
    size_t i = ((size_t)blockIdx.x * 256 + threadIdx.x) * 4;
    float4 x = *(const float4*)(q_in + i);
    float s = x.x + x.y + x.z + x.w;
    #pragma unroll
    for (int o = 16; o; o >>= 1) s += __shfl_xor_sync(0xffffffffu, s, o);
    if ((threadIdx.x & 31) == 0) rs[threadIdx.x >> 5] = s;
    __syncthreads();
    if ((threadIdx.x & 127) == 0) {
        int w0 = threadIdx.x >> 5;
        float t = rs[w0] + rs[w0 + 1] + rs[w0 + 2] + rs[w0 + 3];
        g_qm[i >> 9] = (t != 0.f) ? 1.f : 0.f;
    }
}

// ---------------- kernel 1: tf32 tensor-core GEMM ----------------
// relu(X@W+b) -> fp16 + head row-norms (computed on the fp16-rounded values).
#define GSTAGE_F 8192
#define GEMM_SMEM_BYTES (2 * GSTAGE_F * 4)    // 65536

__global__ __launch_bounds__(256)
void qkv_gemm_tf32(const float* __restrict__ q_in,
                   const float* __restrict__ k_in,
                   const float* __restrict__ v_in,
                   const float* __restrict__ bq,
                   const float* __restrict__ bk,
                   const float* __restrict__ bv) {
    extern __shared__ float gsm[];
    const int z = blockIdx.z;
    const size_t XSZ = (size_t)BDIM * LSEQ * UDIM;
    const float* X = (z == 0) ? q_in : (z == 1) ? k_in : v_in;
    const float* Wt = g_Wt + (size_t)z * UDIM * UDIM;
    const float* bias = (z == 0) ? bq : (z == 1) ? bk : bv;
    __half* Pf = g_Pf + z * XSZ;

    const int tid = threadIdx.x;
    const int wid = tid >> 5;
    const int lane = tid & 31;
    const int wm = wid & 3;
    const int wn = wid >> 2;
    const int m0 = blockIdx.x * 128;
    const int n0 = blockIdx.y * 128;

    auto issue = [&](int kc, int buf) {
        float* st = gsm + buf * GSTAGE_F;
        #pragma unroll
        for (int i = 0; i < 4; i++) {
            int q = tid + i * 256;
            int r = q >> 3, c = q & 7;
            cpa16(st + r * 32 + ((c ^ (r & 7)) << 2),
                  X + (size_t)(m0 + r) * UDIM + kc * 32 + c * 4);
        }
        #pragma unroll
        for (int i = 0; i < 4; i++) {
            int q = tid + i * 256;
            int r = q >> 3, c = q & 7;
            cpa16(st + 4096 + r * 32 + ((c ^ (r & 7)) << 2),
                  Wt + (size_t)(n0 + r) * UDIM + kc * 32 + c * 4);
        }
        CPA_COMMIT();
    };

    float d[2][8][4];
    #pragma unroll
    for (int mf = 0; mf < 2; mf++)
        #pragma unroll
        for (int nf = 0; nf < 8; nf++)
            #pragma unroll
            for (int e = 0; e < 4; e++) d[mf][nf][e] = 0.f;

    const uint32_t smem_u = (uint32_t)__cvta_generic_to_shared(gsm);
    const int arow = wm * 32 + (lane & 15);
    const int aseL = lane >> 4;
    const int brow = wn * 64 + (lane & 7) + ((lane >> 4) << 3);
    const int bseL = (lane >> 3) & 1;

    issue(0, 0);

    for (int kc = 0; kc < 16; kc++) {
        if (kc < 15) { issue(kc + 1, (kc + 1) & 1); CPA_WAIT(1); }
        else         { CPA_WAIT(0); }
        __syncthreads();

        const uint32_t stage_b = smem_u + ((kc & 1) ? GSTAGE_F * 4 : 0);

        #pragma unroll
        for (int s = 0; s < 4; s++) {
            uint32_t a[2][4];
            #pragma unroll
            for (int mf = 0; mf < 2; mf++) {
                int row = arow + mf * 16;
                uint32_t off = (uint32_t)(row * 32 + (((2 * s + aseL) ^ (row & 7)) << 2)) * 4;
                ldsm4(a[mf], stage_b + off);
                cvt_tf32_4(a[mf]);
            }
            uint32_t bfr[4][4];
            #pragma unroll
            for (int ng = 0; ng < 4; ng++) {
                int row = brow + ng * 16;
                uint32_t off = (uint32_t)(4096 * 4) +
                               (uint32_t)(row * 32 + (((2 * s + bseL) ^ (row & 7)) << 2)) * 4;
                ldsm4(bfr[ng], stage_b + off);
            }
            #pragma unroll
            for (int nf = 0; nf < 8; nf++) {
                const uint32_t* bp = &bfr[nf >> 1][(nf & 1) * 2];
                mma_tf32(d[0][nf], a[0], bp);
                mma_tf32(d[1][nf], a[1], bp);
            }
        }
        __syncthreads();
    }

    // epilogue: bias + relu -> fp16 stores; norms from the ROUNDED values
    #pragma unroll
    for (int mf = 0; mf < 2; mf++) {
        int r0 = m0 + wm * 32 + mf * 16 + (lane >> 2);
        int r1 = r0 + 8;
        float ssA = 0.f, ssB = 0.f;
        #pragma unroll
        for (int nf = 0; nf < 8; nf++) {
            int col = n0 + wn * 64 + nf * 8 + (lane & 3) * 2;
            float2 bv2 = *(const float2*)(bias + col);
            float v0 = d[mf][nf][0] + bv2.x; v0 = v0 > 0.f ? v0 : 0.f;
            float v1 = d[mf][nf][1] + bv2.y; v1 = v1 > 0.f ? v1 : 0.f;
            float v2 = d[mf][nf][2] + bv2.x; v2 = v2 > 0.f ? v2 : 0.f;
            float v3 = d[mf][nf][3] + bv2.y; v3 = v3 > 0.f ? v3 : 0.f;
            __half h0 = __float2half_rn(v0), h1 = __float2half_rn(v1);
            __half h2 = __float2half_rn(v2), h3 = __float2half_rn(v3);
            *(__half2*)(Pf + (size_t)r0 * UDIM + col) = __halves2half2(h0, h1);
            *(__half2*)(Pf + (size_t)r1 * UDIM + col) = __halves2half2(h2, h3);
            float r0f = __half2float(h0), r1f = __half2float(h1);
            float r2f = __half2float(h2), r3f = __half2float(h3);
            ssA += r0f * r0f + r1f * r1f;
            ssB += r2f * r2f + r3f * r3f;
        }
        if (z < 2) {
            ssA += __shfl_xor_sync(0xffffffffu, ssA, 1);
            ssA += __shfl_xor_sync(0xffffffffu, ssA, 2);
            ssB += __shfl_xor_sync(0xffffffffu, ssB, 1);
            ssB += __shfl_xor_sync(0xffffffffu, ssB, 2);
            if ((lane & 3) == 0) {
                float* ndst = (z == 0) ? g_Qn : g_Kn;
                int h = blockIdx.y * 2 + wn;
                ndst[h * (BDIM * LSEQ) + r0] = ssA;
                ndst[h * (BDIM * LSEQ) + r1] = ssB;
            }
        }
    }
}

// ---------------- kernel 2: fp16 tensor-core attention, kv-split x2 -------
// Block = 64 q x one hb x half-K (4 tiles), 128 thr = 4 warps x 16q x 64k.
// Single-precision fp16 Q/K/V/P (no hi/lo split). K 2-buf, V 1-buf.
// smem (half el): Q 0 | K 2x4096 @4096 | V @12288 | kn f32 @16384
#define AT_SMEM_HALVES 16384
#define AT_SMEM_BYTES (AT_SMEM_HALVES * 2 + 512 + 256)   // 33536

__global__ __launch_bounds__(128)
void attn_mma(float* __restrict__ score_out) {
    extern __shared__ __half smh[];
    float* kn = (float*)(smh + AT_SMEM_HALVES);
    const int tid = threadIdx.x, lane = tid & 31, wid = tid >> 5;
    const int q0 = blockIdx.x * 64;
    const int hb = blockIdx.y, h = hb >> 2, b = hb & 3;
    const int z = blockIdx.z;
    const size_t XSZ = (size_t)BDIM * LSEQ * UDIM;
    const __half* Qf_g = g_Pf;
    const __half* Kf_g = g_Pf + XSZ;
    const __half* Vf_g = g_Pf + 2 * XSZ;

    auto load_tile = [&](const __half* src, int row0, int dstoff) {
        #pragma unroll
        for (int i = 0; i < 4; i++) {
            int qid = tid + i * 128;
            int r = qid >> 3, c = qid & 7;
            cpa16(smh + dstoff + r * 64 + ((c ^ (r & 7)) << 3),
                  src + (size_t)(b * LSEQ + row0 + r) * UDIM + h * DDIM + c * 8);
        }
    };
    auto issue_K = [&](int tl) {
        int row0 = (z * 4 + tl) * 64;
        load_tile(Kf_g, row0, 4096 + (tl & 1) * 4096);
        if (tid < 16) cpa16(kn + (tl & 1) * 64 + tid * 4,
                            g_Kn + (size_t)h * (BDIM * LSEQ) + b * LSEQ + row0 + tid * 4);
    };
    auto issue_V = [&](int tl) {
        int row0 = (z * 4 + tl) * 64;
        load_tile(Vf_g, row0, 12288);
    };

    // G0: Q + K0 + kn0
    load_tile(Qf_g, q0, 0);
    issue_K(0);
    CPA_COMMIT();

    const int rr = lane >> 2;
    const int qrow = q0 + wid * 16 + rr;
    float qq0 = g_Qn[(size_t)h * (BDIM * LSEQ) + b * LSEQ + qrow];
    float qq1 = g_Qn[(size_t)h * (BDIM * LSEQ) + b * LSEQ + qrow + 8];
    float qm0 = g_qm[b * LSEQ + qrow];
    float qm1 = g_qm[b * LSEQ + qrow + 8];

    const uint32_t smem_u = (uint32_t)__cvta_generic_to_shared(smh);
    const int arow = wid * 16 + (lane & 15);
    const int asel = lane >> 4;
    const int nrow = (lane & 7) + ((lane >> 4) << 3);
    const int nhalf = (lane >> 3) & 1;
    const int vkrow = (lane & 7) + (((lane >> 3) & 1) << 3);
    const int vdsel = lane >> 4;

    uint32_t qf[4][4];
    float o[8][4];
    #pragma unroll
    for (int nf = 0; nf < 8; nf++)
        #pragma unroll
        for (int e = 0; e < 4; e++) o[nf][e] = 0.f;
    float l0 = 0.f, l1 = 0.f;
    const float C8 = 0.18033688f;    // log2(e)/8

    for (int t = 0; t < 4; t++) {
        issue_V(t);
        CPA_COMMIT();
        if (t < 3) issue_K(t + 1);
        CPA_COMMIT();
        CPA_WAIT(2);            // K_t (and Q at t=0) complete
        __syncthreads();

        if (t == 0) {
            #pragma unroll
            for (int ks = 0; ks < 4; ks++) {
                uint32_t aoff = (uint32_t)(arow * 64 + (((ks * 2 + asel) ^ (lane & 7)) << 3)) * 2;
                ldsm4(qf[ks], smem_u + aoff);
            }
        }

        const uint32_t kb = smem_u + (4096 + (t & 1) * 4096) * 2;

        // ---- S = Q.K^T (fp16) ----
        float s[8][4];
        #pragma unroll
        for (int nf = 0; nf < 8; nf++)
            #pragma unroll
            for (int e = 0; e < 4; e++) s[nf][e] = 0.f;
        #pragma unroll
        for (int ks = 0; ks < 4; ks++) {
            uint32_t kh[4][4];
            #pragma unroll
            for (int g = 0; g < 4; g++) {
                uint32_t off = (uint32_t)((g * 16 + nrow) * 64 +
                                          (((ks * 2 + nhalf) ^ (lane & 7)) << 3)) * 2;
                ldsm4(kh[g], kb + off);
            }
            #pragma unroll
            for (int nf = 0; nf < 8; nf++)
                mma_f16(s[nf], qf[ks], &kh[nf >> 1][(nf & 1) * 2]);
        }

        // ---- scores + exp + pack P (fp16) ----
        uint32_t pa[8][2];
        #pragma unroll
        for (int nf = 0; nf < 8; nf++) {
            int c0 = nf * 8 + (lane & 3) * 2;
            float kk0 = kn[(t & 1) * 64 + c0];
            float kk1 = kn[(t & 1) * 64 + c0 + 1];
            float e0 = fmaxf(qq0 + kk0 - 2.f * s[nf][0], 1e-12f);
            float e1 = fmaxf(qq0 + kk1 - 2.f * s[nf][1], 1e-12f);
            float e2 = fmaxf(qq1 + kk0 - 2.f * s[nf][2], 1e-12f);
            float e3 = fmaxf(qq1 + kk1 - 2.f * s[nf][3], 1e-12f);
            float sq0 = sqrt_nm(e0), sq1 = sqrt_nm(e1);
            float sq2 = sqrt_nm(e2), sq3 = sqrt_nm(e3);
            size_t sr0 = ((size_t)(hb * LSEQ + qrow)) * LSEQ + (z * 4 + t) * 64 + c0;
            size_t sr1 = sr0 + (size_t)8 * LSEQ;
            *(float2*)(score_out + sr0) = make_float2(-0.125f * sq0 * qm0, -0.125f * sq1 * qm0);
            *(float2*)(score_out + sr1) = make_float2(-0.125f * sq2 * qm1, -0.125f * sq3 * qm1);
            float p0 = exp2_poly(-C8 * sq0);
            float p1 = exp2_poly(-C8 * sq1);
            float p2 = exp2_poly(-C8 * sq2);
            float p3 = exp2_poly(-C8 * sq3);
            l0 += p0 + p1; l1 += p2 + p3;
            pa[nf][0] = packh2(p0, p1);
            pa[nf][1] = packh2(p2, p3);
        }

        CPA_WAIT(1);            // V_t complete (K_{t+1} may be in flight)
        __syncthreads();

        // ---- O += P.V (fp16) ----
        const uint32_t vb = smem_u + 12288 * 2;
        #pragma unroll
        for (int ks = 0; ks < 4; ks++) {
            uint32_t vh[4][4];
            #pragma unroll
            for (int g = 0; g < 4; g++) {
                int row = ks * 16 + vkrow;
                uint32_t off = (uint32_t)(row * 64 + (((g * 2 + vdsel) ^ (lane & 7)) << 3)) * 2;
                ldsm4t(vh[g], vb + off);
            }
            uint32_t Ah[4] = {pa[2 * ks][0], pa[2 * ks][1], pa[2 * ks + 1][0], pa[2 * ks + 1][1]};
            #pragma unroll
            for (int nf = 0; nf < 8; nf++)
                mma_f16(o[nf], Ah, &vh[nf >> 1][(nf & 1) * 2]);
        }
        __syncthreads();        // V buf & K buf free for next iteration
    }

    // partial l over 64 cols (quad butterfly), write partial O/l
    l0 += __shfl_xor_sync(0xffffffffu, l0, 1);
    l0 += __shfl_xor_sync(0xffffffffu, l0, 2);
    l1 += __shfl_xor_sync(0xffffffffu, l1, 1);
    l1 += __shfl_xor_sync(0xffffffffu, l1, 2);

    size_t prow = (size_t)(z * HBDIM + hb) * LSEQ + qrow;
    #pragma unroll
    for (int nf = 0; nf < 8; nf++) {
        int col = nf * 8 + (lane & 3) * 2;
        *(float2*)(g_Opart + prow * DDIM + col) = make_float2(o[nf][0], o[nf][1]);
        *(float2*)(g_Opart + (prow + 8) * DDIM + col) = make_float2(o[nf][2], o[nf][3]);
    }
    if ((lane & 3) == 0) {
        g_lpart[prow] = l0;
        g_lpart[prow + 8] = l1;
    }
}

// ---------------- kernel 3: combine kv-split halves ----------------
__global__ void combine_kernel(float* __restrict__ out) {
    int g = blockIdx.x * 256 + threadIdx.x;
    int d = (g & 31) * 2;
    int row = g >> 5;                                 // hb*LSEQ + q
    float2 a = *(float2*)(g_Opart + (size_t)row * DDIM + d);
    float2 c = *(float2*)(g_Opart + ((size_t)(HBDIM * LSEQ) + row) * DDIM + d);
    float l = g_lpart[row] + g_lpart[HBDIM * LSEQ + row];
    int hb = row >> 9, q = row & 511;
    int h = hb >> 2, b = hb & 3;
    float s = g_qm[b * LSEQ + q] / l;
    *(float2*)(out + ((size_t)(b * LSEQ + q)) * UDIM + h * DDIM + d) =
        make_float2((a.x + c.x) * s, (a.y + c.y) * s);
}

// ---------------- launcher ----------------
extern "C" void kernel_launch(void* const* d_in, const int* in_sizes, int n_in,
                              void* d_out, int out_size) {
    (void)in_sizes; (void)n_in; (void)out_size;
    const float* queries = (const float*)d_in[0];
    const float* keys    = (const float*)d_in[1];
    const float* values  = (const float*)d_in[2];
    const float* Wq = (const float*)d_in[3];
    const float* bq = (const float*)d_in[4];
    const float* Wk = (const float*)d_in[5];
    const float* bk = (const float*)d_in[6];
    const float* Wv = (const float*)d_in[7];
    const float* bv = (const float*)d_in[8];

    float* out_ptr   = (float*)d_out;
    float* score_ptr = out_ptr + (size_t)BDIM * LSEQ * UDIM;

    cudaFuncSetAttribute(qkv_gemm_tf32, cudaFuncAttributeMaxDynamicSharedMemorySize,
                         GEMM_SMEM_BYTES);
    cudaFuncSetAttribute(attn_mma, cudaFuncAttributeMaxDynamicSharedMemorySize,
                         AT_SMEM_BYTES);

    dim3 twgrid(UDIM / 32, UDIM / 32, 3);
    transpose_w_kernel<<<twgrid, 256>>>(Wq, Wk, Wv);

    qm_kernel<<<(BDIM * LSEQ * UDIM) / (256 * 4), 256>>>(queries);

    dim3 ggrid(BDIM * LSEQ / 128, UDIM / 128, 3);
    qkv_gemm_tf32<<<ggrid, 256, GEMM_SMEM_BYTES>>>(queries, keys, values, bq, bk, bv);

    dim3 agrid(LSEQ / 64, HBDIM, 2);
    attn_mma<<<agrid, 128, AT_SMEM_BYTES>>>(score_ptr);

    combine_kernel<<<(HBDIM * LSEQ * DDIM / 2) / 256, 256>>>(out_ptr);
}

// round 16
// speedup vs baseline: 5.0149x; 1.2549x over previous
#include <cuda_runtime.h>
#include <cuda_fp16.h>
#include <cstdint>

#define LSEQ 512
#define UDIM 512
#define BDIM 4
#define HDIM 8
#define DDIM 64
#define HBDIM 32

// ---------------- scratch (device globals, no allocation) ----------------
__device__ float g_qm[BDIM * LSEQ];
__device__ float g_Qn[HDIM * BDIM * LSEQ];
__device__ float g_Kn[HDIM * BDIM * LSEQ];
__device__ __half g_Xf[3 * BDIM * LSEQ * UDIM];       // fp16 inputs [z][m][u]
__device__ __half g_Wth[3 * UDIM * UDIM];             // fp16 W^T [z][n][k]
__device__ __half g_Pf[3 * BDIM * LSEQ * UDIM];       // projected Q/K/V, fp16
__device__ float g_Opart[2 * HBDIM * LSEQ * DDIM];    // kv-split partial O
__device__ float g_lpart[2 * HBDIM * LSEQ];

// ---------------- helpers ----------------
__device__ __forceinline__ float sqrt_nm(float x) {
    float r = __int_as_float(0x5f3759df - (__float_as_int(x) >> 1));
    r = r * (1.5f - 0.5f * x * r * r);
    r = r * (1.5f - 0.5f * x * r * r);
    return x * r;
}
__device__ __forceinline__ float exp2_poly(float y) {
    y = fmaxf(y, -120.f);
    float fn = y + 12582912.f;
    int ib = __float_as_int(fn);
    float n = fn - 12582912.f;
    float f = y - n;
    float scale = __int_as_float((ib - 0x4B400000 + 127) << 23);
    float p = 0.0013333558f;
    p = fmaf(p, f, 0.0096181291f);
    p = fmaf(p, f, 0.0555041087f);
    p = fmaf(p, f, 0.2402265069f);
    p = fmaf(p, f, 0.6931471806f);
    p = fmaf(p, f, 1.0f);
    return scale * p;
}
__device__ __forceinline__ void cpa16(void* sdst, const void* gsrc) {
    uint32_t s = (uint32_t)__cvta_generic_to_shared(sdst);
    asm volatile("cp.async.cg.shared.global [%0], [%1], 16;" :: "r"(s), "l"(gsrc));
}
#define CPA_COMMIT() asm volatile("cp.async.commit_group;")
#define CPA_WAIT(n)  asm volatile("cp.async.wait_group %0;" :: "n"(n))

__device__ __forceinline__ void ldsm4(uint32_t* r, uint32_t addr) {
    asm volatile("ldmatrix.sync.aligned.m8n8.x4.shared.b16 {%0,%1,%2,%3}, [%4];"
                 : "=r"(r[0]), "=r"(r[1]), "=r"(r[2]), "=r"(r[3]) : "r"(addr));
}
__device__ __forceinline__ void ldsm4t(uint32_t* r, uint32_t addr) {
    asm volatile("ldmatrix.sync.aligned.m8n8.x4.trans.shared.b16 {%0,%1,%2,%3}, [%4];"
                 : "=r"(r[0]), "=r"(r[1]), "=r"(r[2]), "=r"(r[3]) : "r"(addr));
}
__device__ __forceinline__ void mma_f16(float* d, const uint32_t* a, const uint32_t* b) {
    asm volatile(
        "mma.sync.aligned.m16n8k16.row.col.f32.f16.f16.f32 "
        "{%0,%1,%2,%3}, {%4,%5,%6,%7}, {%8,%9}, {%0,%1,%2,%3};"
        : "+f"(d[0]), "+f"(d[1]), "+f"(d[2]), "+f"(d[3])
        : "r"(a[0]), "r"(a[1]), "r"(a[2]), "r"(a[3]), "r"(b[0]), "r"(b[1]));
}
__device__ __forceinline__ uint32_t packh2(float lo, float hi) {
    __half2 h = __floats2half2_rn(lo, hi);
    return *reinterpret_cast<uint32_t*>(&h);
}

// ---------------- kernel A: convert X -> fp16, fused query mask -----------
__global__ void prep_x_kernel(const float* __restrict__ q,
                              const float* __restrict__ k,
                              const float* __restrict__ v) {
    __shared__ float rs[8];
    int z = blockIdx.y;
    const float* src = (z == 0) ? q : (z == 1) ? k : v;
    __half* dst = g_Xf + (size_t)z * (BDIM * LSEQ * UDIM);
    size_t i = ((size_t)blockIdx.x * 256 + threadIdx.x) * 4;
    float4 x = *(const float4*)(src + i);
    __half2 h0 = __floats2half2_rn(x.x, x.y);
    __half2 h1 = __floats2half2_rn(x.z, x.w);
    *(__half2*)(dst + i) = h0;
    *(__half2*)(dst + i + 2) = h1;

    if (z == 0) {            // qm: one row = 128 threads (512 floats)
        float s = x.x + x.y + x.z + x.w;
        #pragma unroll
        for (int o = 16; o; o >>= 1) s += __shfl_xor_sync(0xffffffffu, s, o);
        if ((threadIdx.x & 31) == 0) rs[threadIdx.x >> 5] = s;
        __syncthreads();
        if ((threadIdx.x & 127) == 0) {
            int w0 = threadIdx.x >> 5;
            float t = rs[w0] + rs[w0 + 1] + rs[w0 + 2] + rs[w0 + 3];
            g_qm[i >> 9] = (t != 0.f) ? 1.f : 0.f;
        }
    }
}

// ---------------- kernel B: transpose W -> [n][k] fp16 ----------------
__global__ void transpose_w_kernel(const float* __restrict__ Wq,
                                   const float* __restrict__ Wk,
                                   const float* __restrict__ Wv) {
    __shared__ float t[32][33];
    int z = blockIdx.z;
    const float* W = (z == 0) ? Wq : (z == 1) ? Wk : Wv;
    __half* D = g_Wth + (size_t)z * UDIM * UDIM;
    int k0 = blockIdx.x * 32;
    int n0 = blockIdx.y * 32;
    int tx = threadIdx.x & 31, ty = threadIdx.x >> 5;
    #pragma unroll
    for (int i = 0; i < 4; i++) {
        int r = ty + i * 8;
        t[r][tx] = W[(size_t)(k0 + r) * UDIM + n0 + tx];
    }
    __syncthreads();
    #pragma unroll
    for (int i = 0; i < 4; i++) {
        int r = ty + i * 8;
        D[(size_t)(n0 + r) * UDIM + k0 + tx] = __float2half_rn(t[tx][r]);
    }
}

// ---------------- kernel 1: fp16 tensor-core GEMM ----------------
// relu(X@W+b) -> fp16 + head row-norms on the rounded values.
// Tile M=128, N=128, K-chunk 64 fp16. 256 thr = 8 warps (4m x 2n).
#define GT_TILE_H (128 * 64)                      // halves per tile
#define GT_STAGE_H (2 * GT_TILE_H)                // A + B
#define GEMM_SMEM_BYTES (2 * GT_STAGE_H * 2)      // 65536

__global__ __launch_bounds__(256)
void qkv_gemm_f16(const float* __restrict__ bq,
                  const float* __restrict__ bk,
                  const float* __restrict__ bv) {
    extern __shared__ __half gsm[];
    const int z = blockIdx.z;
    const size_t XSZ = (size_t)BDIM * LSEQ * UDIM;
    const __half* X = g_Xf + z * XSZ;
    const __half* Wt = g_Wth + (size_t)z * UDIM * UDIM;
    const float* bias = (z == 0) ? bq : (z == 1) ? bk : bv;
    __half* Pf = g_Pf + z * XSZ;

    const int tid = threadIdx.x;
    const int wid = tid >> 5;
    const int lane = tid & 31;
    const int wm = wid & 3;
    const int wn = wid >> 2;
    const int m0 = blockIdx.x * 128;
    const int n0 = blockIdx.y * 128;

    auto issue = [&](int kc, int buf) {
        __half* st = gsm + buf * GT_STAGE_H;
        #pragma unroll
        for (int i = 0; i < 4; i++) {               // A: 128 rows x 8 chunks
            int q = tid + i * 256;
            int r = q >> 3, c = q & 7;
            cpa16(st + r * 64 + ((c ^ (r & 7)) << 3),
                  X + (size_t)(m0 + r) * UDIM + kc * 64 + c * 8);
        }
        #pragma unroll
        for (int i = 0; i < 4; i++) {               // B: 128 rows x 8 chunks
            int q = tid + i * 256;
            int r = q >> 3, c = q & 7;
            cpa16(st + GT_TILE_H + r * 64 + ((c ^ (r & 7)) << 3),
                  Wt + (size_t)(n0 + r) * UDIM + kc * 64 + c * 8);
        }
        CPA_COMMIT();
    };

    float d[2][8][4];
    #pragma unroll
    for (int mf = 0; mf < 2; mf++)
        #pragma unroll
        for (int nf = 0; nf < 8; nf++)
            #pragma unroll
            for (int e = 0; e < 4; e++) d[mf][nf][e] = 0.f;

    const uint32_t smem_u = (uint32_t)__cvta_generic_to_shared(gsm);
    const int arow = wm * 32 + (lane & 15);          // + mf*16
    const int ahalf = lane >> 4;
    const int asw = arow & 7;
    const int brow = wn * 64 + (lane & 7) + ((lane >> 4) << 3);   // + ng*16
    const int bhalf = (lane >> 3) & 1;
    const int bsw = brow & 7;

    issue(0, 0);

    for (int kc = 0; kc < 8; kc++) {
        if (kc < 7) { issue(kc + 1, (kc + 1) & 1); CPA_WAIT(1); }
        else        { CPA_WAIT(0); }
        __syncthreads();

        const uint32_t stage_b = smem_u + ((kc & 1) ? GT_STAGE_H * 2 : 0);

        #pragma unroll
        for (int k16 = 0; k16 < 4; k16++) {
            uint32_t a[2][4];
            #pragma unroll
            for (int mf = 0; mf < 2; mf++) {
                uint32_t aoff = (uint32_t)((arow + mf * 16) * 64 +
                                           (((k16 * 2 + ahalf) ^ asw) << 3)) * 2;
                ldsm4(a[mf], stage_b + aoff);
            }
            uint32_t bfr[4][4];
            #pragma unroll
            for (int ng = 0; ng < 4; ng++) {
                uint32_t boff = (uint32_t)((brow + ng * 16) * 64 +
                                           (((k16 * 2 + bhalf) ^ bsw) << 3)) * 2;
                ldsm4(bfr[ng], stage_b + GT_TILE_H * 2 + boff);
            }
            #pragma unroll
            for (int nf = 0; nf < 8; nf++) {
                const uint32_t* bp = &bfr[nf >> 1][(nf & 1) * 2];
                mma_f16(d[0][nf], a[0], bp);
                mma_f16(d[1][nf], a[1], bp);
            }
        }
        __syncthreads();
    }

    // epilogue: bias + relu -> fp16 stores; norms from the ROUNDED values
    #pragma unroll
    for (int mf = 0; mf < 2; mf++) {
        int r0 = m0 + wm * 32 + mf * 16 + (lane >> 2);
        int r1 = r0 + 8;
        float ssA = 0.f, ssB = 0.f;
        #pragma unroll
        for (int nf = 0; nf < 8; nf++) {
            int col = n0 + wn * 64 + nf * 8 + (lane & 3) * 2;
            float2 bv2 = *(const float2*)(bias + col);
            float v0 = d[mf][nf][0] + bv2.x; v0 = v0 > 0.f ? v0 : 0.f;
            float v1 = d[mf][nf][1] + bv2.y; v1 = v1 > 0.f ? v1 : 0.f;
            float v2 = d[mf][nf][2] + bv2.x; v2 = v2 > 0.f ? v2 : 0.f;
            float v3 = d[mf][nf][3] + bv2.y; v3 = v3 > 0.f ? v3 : 0.f;
            __half h0 = __float2half_rn(v0), h1 = __float2half_rn(v1);
            __half h2 = __float2half_rn(v2), h3 = __float2half_rn(v3);
            *(__half2*)(Pf + (size_t)r0 * UDIM + col) = __halves2half2(h0, h1);
            *(__half2*)(Pf + (size_t)r1 * UDIM + col) = __halves2half2(h2, h3);
            float r0f = __half2float(h0), r1f = __half2float(h1);
            float r2f = __half2float(h2), r3f = __half2float(h3);
            ssA += r0f * r0f + r1f * r1f;
            ssB += r2f * r2f + r3f * r3f;
        }
        if (z < 2) {
            ssA += __shfl_xor_sync(0xffffffffu, ssA, 1);
            ssA += __shfl_xor_sync(0xffffffffu, ssA, 2);
            ssB += __shfl_xor_sync(0xffffffffu, ssB, 1);
            ssB += __shfl_xor_sync(0xffffffffu, ssB, 2);
            if ((lane & 3) == 0) {
                float* ndst = (z == 0) ? g_Qn : g_Kn;
                int h = blockIdx.y * 2 + wn;
                ndst[h * (BDIM * LSEQ) + r0] = ssA;
                ndst[h * (BDIM * LSEQ) + r1] = ssB;
            }
        }
    }
}

// ---------------- kernel 2: fp16 tensor-core attention, kv-split x2 -------
// (verbatim from passing R14)
#define AT_SMEM_HALVES 16384
#define AT_SMEM_BYTES (AT_SMEM_HALVES * 2 + 512 + 256)   // 33536

__global__ __launch_bounds__(128)
void attn_mma(float* __restrict__ score_out) {
    extern __shared__ __half smh[];
    float* kn = (float*)(smh + AT_SMEM_HALVES);
    const int tid = threadIdx.x, lane = tid & 31, wid = tid >> 5;
    const int q0 = blockIdx.x * 64;
    const int hb = blockIdx.y, h = hb >> 2, b = hb & 3;
    const int z = blockIdx.z;
    const size_t XSZ = (size_t)BDIM * LSEQ * UDIM;
    const __half* Qf_g = g_Pf;
    const __half* Kf_g = g_Pf + XSZ;
    const __half* Vf_g = g_Pf + 2 * XSZ;

    auto load_tile = [&](const __half* src, int row0, int dstoff) {
        #pragma unroll
        for (int i = 0; i < 4; i++) {
            int qid = tid + i * 128;
            int r = qid >> 3, c = qid & 7;
            cpa16(smh + dstoff + r * 64 + ((c ^ (r & 7)) << 3),
                  src + (size_t)(b * LSEQ + row0 + r) * UDIM + h * DDIM + c * 8);
        }
    };
    auto issue_K = [&](int tl) {
        int row0 = (z * 4 + tl) * 64;
        load_tile(Kf_g, row0, 4096 + (tl & 1) * 4096);
        if (tid < 16) cpa16(kn + (tl & 1) * 64 + tid * 4,
                            g_Kn + (size_t)h * (BDIM * LSEQ) + b * LSEQ + row0 + tid * 4);
    };
    auto issue_V = [&](int tl) {
        int row0 = (z * 4 + tl) * 64;
        load_tile(Vf_g, row0, 12288);
    };

    load_tile(Qf_g, q0, 0);
    issue_K(0);
    CPA_COMMIT();

    const int rr = lane >> 2;
    const int qrow = q0 + wid * 16 + rr;
    float qq0 = g_Qn[(size_t)h * (BDIM * LSEQ) + b * LSEQ + qrow];
    float qq1 = g_Qn[(size_t)h * (BDIM * LSEQ) + b * LSEQ + qrow + 8];
    float qm0 = g_qm[b * LSEQ + qrow];
    float qm1 = g_qm[b * LSEQ + qrow + 8];

    const uint32_t smem_u = (uint32_t)__cvta_generic_to_shared(smh);
    const int arow = wid * 16 + (lane & 15);
    const int asel = lane >> 4;
    const int nrow = (lane & 7) + ((lane >> 4) << 3);
    const int nhalf = (lane >> 3) & 1;
    const int vkrow = (lane & 7) + (((lane >> 3) & 1) << 3);
    const int vdsel = lane >> 4;

    uint32_t qf[4][4];
    float o[8][4];
    #pragma unroll
    for (int nf = 0; nf < 8; nf++)
        #pragma unroll
        for (int e = 0; e < 4; e++) o[nf][e] = 0.f;
    float l0 = 0.f, l1 = 0.f;
    const float C8 = 0.18033688f;    // log2(e)/8

    for (int t = 0; t < 4; t++) {
        issue_V(t);
        CPA_COMMIT();
        if (t < 3) issue_K(t + 1);
        CPA_COMMIT();
        CPA_WAIT(2);
        __syncthreads();

        if (t == 0) {
            #pragma unroll
            for (int ks = 0; ks < 4; ks++) {
                uint32_t aoff = (uint32_t)(arow * 64 + (((ks * 2 + asel) ^ (lane & 7)) << 3)) * 2;
                ldsm4(qf[ks], smem_u + aoff);
            }
        }

        const uint32_t kb = smem_u + (4096 + (t & 1) * 4096) * 2;

        float s[8][4];
        #pragma unroll
        for (int nf = 0; nf < 8; nf++)
            #pragma unroll
            for (int e = 0; e < 4; e++) s[nf][e] = 0.f;
        #pragma unroll
        for (int ks = 0; ks < 4; ks++) {
            uint32_t kh[4][4];
            #pragma unroll
            for (int g = 0; g < 4; g++) {
                uint32_t off = (uint32_t)((g * 16 + nrow) * 64 +
                                          (((ks * 2 + nhalf) ^ (lane & 7)) << 3)) * 2;
                ldsm4(kh[g], kb + off);
            }
            #pragma unroll
            for (int nf = 0; nf < 8; nf++)
                mma_f16(s[nf], qf[ks], &kh[nf >> 1][(nf & 1) * 2]);
        }

        uint32_t pa[8][2];
        #pragma unroll
        for (int nf = 0; nf < 8; nf++) {
            int c0 = nf * 8 + (lane & 3) * 2;
            float kk0 = kn[(t & 1) * 64 + c0];
            float kk1 = kn[(t & 1) * 64 + c0 + 1];
            float e0 = fmaxf(qq0 + kk0 - 2.f * s[nf][0], 1e-12f);
            float e1 = fmaxf(qq0 + kk1 - 2.f * s[nf][1], 1e-12f);
            float e2 = fmaxf(qq1 + kk0 - 2.f * s[nf][2], 1e-12f);
            float e3 = fmaxf(qq1 + kk1 - 2.f * s[nf][3], 1e-12f);
            float sq0 = sqrt_nm(e0), sq1 = sqrt_nm(e1);
            float sq2 = sqrt_nm(e2), sq3 = sqrt_nm(e3);
            size_t sr0 = ((size_t)(hb * LSEQ + qrow)) * LSEQ + (z * 4 + t) * 64 + c0;
            size_t sr1 = sr0 + (size_t)8 * LSEQ;
            *(float2*)(score_out + sr0) = make_float2(-0.125f * sq0 * qm0, -0.125f * sq1 * qm0);
            *(float2*)(score_out + sr1) = make_float2(-0.125f * sq2 * qm1, -0.125f * sq3 * qm1);
            float p0 = exp2_poly(-C8 * sq0);
            float p1 = exp2_poly(-C8 * sq1);
            float p2 = exp2_poly(-C8 * sq2);
            float p3 = exp2_poly(-C8 * sq3);
            l0 += p0 + p1; l1 += p2 + p3;
            pa[nf][0] = packh2(p0, p1);
            pa[nf][1] = packh2(p2, p3);
        }

        CPA_WAIT(1);
        __syncthreads();

        const uint32_t vb = smem_u + 12288 * 2;
        #pragma unroll
        for (int ks = 0; ks < 4; ks++) {
            uint32_t vh[4][4];
            #pragma unroll
            for (int g = 0; g < 4; g++) {
                int row = ks * 16 + vkrow;
                uint32_t off = (uint32_t)(row * 64 + (((g * 2 + vdsel) ^ (lane & 7)) << 3)) * 2;
                ldsm4t(vh[g], vb + off);
            }
            uint32_t Ah[4] = {pa[2 * ks][0], pa[2 * ks][1], pa[2 * ks + 1][0], pa[2 * ks + 1][1]};
            #pragma unroll
            for (int nf = 0; nf < 8; nf++)
                mma_f16(o[nf], Ah, &vh[nf >> 1][(nf & 1) * 2]);
        }
        __syncthreads();
    }

    l0 += __shfl_xor_sync(0xffffffffu, l0, 1);
    l0 += __shfl_xor_sync(0xffffffffu, l0, 2);
    l1 += __shfl_xor_sync(0xffffffffu, l1, 1);
    l1 += __shfl_xor_sync(0xffffffffu, l1, 2);

    size_t prow = (size_t)(z * HBDIM + hb) * LSEQ + qrow;
    #pragma unroll
    for (int nf = 0; nf < 8; nf++) {
        int col = nf * 8 + (lane & 3) * 2;
        *(float2*)(g_Opart + prow * DDIM + col) = make_float2(o[nf][0], o[nf][1]);
        *(float2*)(g_Opart + (prow + 8) * DDIM + col) = make_float2(o[nf][2], o[nf][3]);
    }
    if ((lane & 3) == 0) {
        g_lpart[prow] = l0;
        g_lpart[prow + 8] = l1;
    }
}

// ---------------- kernel 3: combine kv-split halves ----------------
__global__ void combine_kernel(float* __restrict__ out) {
    int g = blockIdx.x * 256 + threadIdx.x;
    int d = (g & 31) * 2;
    int row = g >> 5;                                 // hb*LSEQ + q
    float2 a = *(float2*)(g_Opart + (size_t)row * DDIM + d);
    float2 c = *(float2*)(g_Opart + ((size_t)(HBDIM * LSEQ) + row) * DDIM + d);
    float l = g_lpart[row] + g_lpart[HBDIM * LSEQ + row];
    int hb = row >> 9, q = row & 511;
    int h = hb >> 2, b = hb & 3;
    float s = g_qm[b * LSEQ + q] / l;
    *(float2*)(out + ((size_t)(b * LSEQ + q)) * UDIM + h * DDIM + d) =
        make_float2((a.x + c.x) * s, (a.y + c.y) * s);
}

// ---------------- launcher ----------------
extern "C" void kernel_launch(void* const* d_in, const int* in_sizes, int n_in,
                              void* d_out, int out_size) {
    (void)in_sizes; (void)n_in; (void)out_size;
    const float* queries = (const float*)d_in[0];
    const float* keys    = (const float*)d_in[1];
    const float* values  = (const float*)d_in[2];
    const float* Wq = (const float*)d_in[3];
    const float* bq = (const float*)d_in[4];
    const float* Wk = (const float*)d_in[5];
    const float* bk = (const float*)d_in[6];
    const float* Wv = (const float*)d_in[7];
    const float* bv = (const float*)d_in[8];

    float* out_ptr   = (float*)d_out;
    float* score_ptr = out_ptr + (size_t)BDIM * LSEQ * UDIM;

    cudaFuncSetAttribute(qkv_gemm_f16, cudaFuncAttributeMaxDynamicSharedMemorySize,
                         GEMM_SMEM_BYTES);
    cudaFuncSetAttribute(attn_mma, cudaFuncAttributeMaxDynamicSharedMemorySize,
                         AT_SMEM_BYTES);

    dim3 pxgrid((BDIM * LSEQ * UDIM) / (256 * 4), 3);
    prep_x_kernel<<<pxgrid, 256>>>(queries, keys, values);

    dim3 twgrid(UDIM / 32, UDIM / 32, 3);
    transpose_w_kernel<<<twgrid, 256>>>(Wq, Wk, Wv);

    dim3 ggrid(BDIM * LSEQ / 128, UDIM / 128, 3);
    qkv_gemm_f16<<<ggrid, 256, GEMM_SMEM_BYTES>>>(bq, bk, bv);

    dim3 agrid(LSEQ / 64, HBDIM, 2);
    attn_mma<<<agrid, 128, AT_SMEM_BYTES>>>(score_ptr);

    combine_kernel<<<(HBDIM * LSEQ * DDIM / 2) / 256, 256>>>(out_ptr);
}

// round 17
// speedup vs baseline: 5.0183x; 1.0007x over previous
#include <cuda_runtime.h>
#include <cuda_fp16.h>
#include <cstdint>

#define LSEQ 512
#define UDIM 512
#define BDIM 4
#define HDIM 8
#define DDIM 64
#define HBDIM 32

// ---------------- scratch (device globals, no allocation) ----------------
__device__ float g_qm[BDIM * LSEQ];
__device__ float g_Qn[HDIM * BDIM * LSEQ];
__device__ float g_Kn[HDIM * BDIM * LSEQ];
__device__ __half g_Xf[3 * BDIM * LSEQ * UDIM];       // fp16 inputs [z][m][u]
__device__ __half g_Wth[3 * UDIM * UDIM];             // fp16 W^T [z][n][k]
__device__ __half g_Pf[3 * BDIM * LSEQ * UDIM];       // projected Q/K/V, fp16
__device__ float g_Opart[2 * HBDIM * LSEQ * DDIM];    // kv-split partial O
__device__ float g_lpart[2 * HBDIM * LSEQ];

// ---------------- helpers ----------------
__device__ __forceinline__ float sqrt_nm(float x) {
    float r = __int_as_float(0x5f3759df - (__float_as_int(x) >> 1));
    r = r * (1.5f - 0.5f * x * r * r);
    r = r * (1.5f - 0.5f * x * r * r);
    return x * r;
}
// degree-4 exp2 for y <= 0 (truncated deg-5; extra err ~4e-5 rel)
__device__ __forceinline__ float exp2_poly(float y) {
    y = fmaxf(y, -120.f);
    float fn = y + 12582912.f;
    int ib = __float_as_int(fn);
    float n = fn - 12582912.f;
    float f = y - n;
    float scale = __int_as_float((ib - 0x4B400000 + 127) << 23);
    float p = 0.0096181291f;
    p = fmaf(p, f, 0.0555041087f);
    p = fmaf(p, f, 0.2402265069f);
    p = fmaf(p, f, 0.6931471806f);
    p = fmaf(p, f, 1.0f);
    return scale * p;
}
__device__ __forceinline__ void cpa16(void* sdst, const void* gsrc) {
    uint32_t s = (uint32_t)__cvta_generic_to_shared(sdst);
    asm volatile("cp.async.cg.shared.global [%0], [%1], 16;" :: "r"(s), "l"(gsrc));
}
#define CPA_COMMIT() asm volatile("cp.async.commit_group;")
#define CPA_WAIT(n)  asm volatile("cp.async.wait_group %0;" :: "n"(n))

__device__ __forceinline__ void ldsm4(uint32_t* r, uint32_t addr) {
    asm volatile("ldmatrix.sync.aligned.m8n8.x4.shared.b16 {%0,%1,%2,%3}, [%4];"
                 : "=r"(r[0]), "=r"(r[1]), "=r"(r[2]), "=r"(r[3]) : "r"(addr));
}
__device__ __forceinline__ void ldsm4t(uint32_t* r, uint32_t addr) {
    asm volatile("ldmatrix.sync.aligned.m8n8.x4.trans.shared.b16 {%0,%1,%2,%3}, [%4];"
                 : "=r"(r[0]), "=r"(r[1]), "=r"(r[2]), "=r"(r[3]) : "r"(addr));
}
__device__ __forceinline__ void mma_f16(float* d, const uint32_t* a, const uint32_t* b) {
    asm volatile(
        "mma.sync.aligned.m16n8k16.row.col.f32.f16.f16.f32 "
        "{%0,%1,%2,%3}, {%4,%5,%6,%7}, {%8,%9}, {%0,%1,%2,%3};"
        : "+f"(d[0]), "+f"(d[1]), "+f"(d[2]), "+f"(d[3])
        : "r"(a[0]), "r"(a[1]), "r"(a[2]), "r"(a[3]), "r"(b[0]), "r"(b[1]));
}
__device__ __forceinline__ uint32_t packh2(float lo, float hi) {
    __half2 h = __floats2half2_rn(lo, hi);
    return *reinterpret_cast<uint32_t*>(&h);
}

// ---------------- kernel A: convert X -> fp16, fused query mask -----------
__global__ void prep_x_kernel(const float* __restrict__ q,
                              const float* __restrict__ k,
                              const float* __restrict__ v) {
    __shared__ float rs[8];
    int z = blockIdx.y;
    const float* src = (z == 0) ? q : (z == 1) ? k : v;
    __half* dst = g_Xf + (size_t)z * (BDIM * LSEQ * UDIM);
    size_t i = ((size_t)blockIdx.x * 256 + threadIdx.x) * 4;
    float4 x = *(const float4*)(src + i);
    __half2 h0 = __floats2half2_rn(x.x, x.y);
    __half2 h1 = __floats2half2_rn(x.z, x.w);
    *(__half2*)(dst + i) = h0;
    *(__half2*)(dst + i + 2) = h1;

    if (z == 0) {
        float s = x.x + x.y + x.z + x.w;
        #pragma unroll
        for (int o = 16; o; o >>= 1) s += __shfl_xor_sync(0xffffffffu, s, o);
        if ((threadIdx.x & 31) == 0) rs[threadIdx.x >> 5] = s;
        __syncthreads();
        if ((threadIdx.x & 127) == 0) {
            int w0 = threadIdx.x >> 5;
            float t = rs[w0] + rs[w0 + 1] + rs[w0 + 2] + rs[w0 + 3];
            g_qm[i >> 9] = (t != 0.f) ? 1.f : 0.f;
        }
    }
}

// ---------------- kernel B: transpose W -> [n][k] fp16 ----------------
__global__ void transpose_w_kernel(const float* __restrict__ Wq,
                                   const float* __restrict__ Wk,
                                   const float* __restrict__ Wv) {
    __shared__ float t[32][33];
    int z = blockIdx.z;
    const float* W = (z == 0) ? Wq : (z == 1) ? Wk : Wv;
    __half* D = g_Wth + (size_t)z * UDIM * UDIM;
    int k0 = blockIdx.x * 32;
    int n0 = blockIdx.y * 32;
    int tx = threadIdx.x & 31, ty = threadIdx.x >> 5;
    #pragma unroll
    for (int i = 0; i < 4; i++) {
        int r = ty + i * 8;
        t[r][tx] = W[(size_t)(k0 + r) * UDIM + n0 + tx];
    }
    __syncthreads();
    #pragma unroll
    for (int i = 0; i < 4; i++) {
        int r = ty + i * 8;
        D[(size_t)(n0 + r) * UDIM + k0 + tx] = __float2half_rn(t[tx][r]);
    }
}

// ---------------- kernel 1: fp16 tensor-core GEMM (BM=128, BN=64) --------
// relu(X@W+b) -> fp16 + head row-norms. One head per block (BN=64).
// 384 blocks (16 x 8 x 3), 256 thr = 8 warps x 16 rows, warp tile 16x64.
#define GA_TILE_H (128 * 64)                      // A halves per stage
#define GB_TILE_H (64 * 64)                       // B halves per stage
#define GT2_STAGE_H (GA_TILE_H + GB_TILE_H)       // 12288
#define GEMM_SMEM_BYTES (2 * GT2_STAGE_H * 2)     // 49152

__global__ __launch_bounds__(256)
void qkv_gemm_f16(const float* __restrict__ bq,
                  const float* __restrict__ bk,
                  const float* __restrict__ bv) {
    extern __shared__ __half gsm[];
    const int z = blockIdx.z;
    const size_t XSZ = (size_t)BDIM * LSEQ * UDIM;
    const __half* X = g_Xf + z * XSZ;
    const __half* Wt = g_Wth + (size_t)z * UDIM * UDIM;
    const float* bias = (z == 0) ? bq : (z == 1) ? bk : bv;
    __half* Pf = g_Pf + z * XSZ;

    const int tid = threadIdx.x;
    const int wm = tid >> 5;        // 0..7, 16 rows each
    const int lane = tid & 31;
    const int m0 = blockIdx.x * 128;
    const int n0 = blockIdx.y * 64;
    const int hh = blockIdx.y;      // head index (BN == DDIM)

    auto issue = [&](int kc, int buf) {
        __half* st = gsm + buf * GT2_STAGE_H;
        #pragma unroll
        for (int i = 0; i < 4; i++) {               // A: 128 rows x 8 chunks
            int q = tid + i * 256;
            int r = q >> 3, c = q & 7;
            cpa16(st + r * 64 + ((c ^ (r & 7)) << 3),
                  X + (size_t)(m0 + r) * UDIM + kc * 64 + c * 8);
        }
        #pragma unroll
        for (int i = 0; i < 2; i++) {               // B: 64 rows x 8 chunks
            int q = tid + i * 256;
            int r = q >> 3, c = q & 7;
            cpa16(st + GA_TILE_H + r * 64 + ((c ^ (r & 7)) << 3),
                  Wt + (size_t)(n0 + r) * UDIM + kc * 64 + c * 8);
        }
        CPA_COMMIT();
    };

    float d[8][4];
    #pragma unroll
    for (int nf = 0; nf < 8; nf++)
        #pragma unroll
        for (int e = 0; e < 4; e++) d[nf][e] = 0.f;

    const uint32_t smem_u = (uint32_t)__cvta_generic_to_shared(gsm);
    const int arow = wm * 16 + (lane & 15);
    const int ahalf = lane >> 4;
    const int asw = arow & 7;
    const int brow = (lane & 7) + ((lane >> 4) << 3);   // + ng*16
    const int bhalf = (lane >> 3) & 1;

    issue(0, 0);

    for (int kc = 0; kc < 8; kc++) {
        if (kc < 7) { issue(kc + 1, (kc + 1) & 1); CPA_WAIT(1); }
        else        { CPA_WAIT(0); }
        __syncthreads();

        const uint32_t stage_b = smem_u + ((kc & 1) ? GT2_STAGE_H * 2 : 0);

        #pragma unroll
        for (int k16 = 0; k16 < 4; k16++) {
            uint32_t a[4];
            {
                uint32_t aoff = (uint32_t)(arow * 64 +
                                           (((k16 * 2 + ahalf) ^ asw) << 3)) * 2;
                ldsm4(a, stage_b + aoff);
            }
            uint32_t bfr[4][4];
            #pragma unroll
            for (int ng = 0; ng < 4; ng++) {
                int row = brow + ng * 16;
                uint32_t boff = (uint32_t)(GA_TILE_H * 2) +
                                (uint32_t)(row * 64 + (((k16 * 2 + bhalf) ^ (row & 7)) << 3)) * 2;
                ldsm4(bfr[ng], stage_b + boff);
            }
            #pragma unroll
            for (int nf = 0; nf < 8; nf++)
                mma_f16(d[nf], a, &bfr[nf >> 1][(nf & 1) * 2]);
        }
        __syncthreads();
    }

    // epilogue: bias + relu -> fp16 stores; norms on ROUNDED values (warp-local head)
    {
        int r0 = m0 + wm * 16 + (lane >> 2);
        int r1 = r0 + 8;
        float ss0 = 0.f, ss1 = 0.f;
        #pragma unroll
        for (int nf = 0; nf < 8; nf++) {
            int col = n0 + nf * 8 + (lane & 3) * 2;
            float2 bv2 = *(const float2*)(bias + col);
            float v0 = d[nf][0] + bv2.x; v0 = v0 > 0.f ? v0 : 0.f;
            float v1 = d[nf][1] + bv2.y; v1 = v1 > 0.f ? v1 : 0.f;
            float v2 = d[nf][2] + bv2.x; v2 = v2 > 0.f ? v2 : 0.f;
            float v3 = d[nf][3] + bv2.y; v3 = v3 > 0.f ? v3 : 0.f;
            __half h0 = __float2half_rn(v0), h1 = __float2half_rn(v1);
            __half h2 = __float2half_rn(v2), h3 = __float2half_rn(v3);
            *(__half2*)(Pf + (size_t)r0 * UDIM + col) = __halves2half2(h0, h1);
            *(__half2*)(Pf + (size_t)r1 * UDIM + col) = __halves2half2(h2, h3);
            float f0 = __half2float(h0), f1 = __half2float(h1);
            float f2 = __half2float(h2), f3 = __half2float(h3);
            ss0 += f0 * f0 + f1 * f1;
            ss1 += f2 * f2 + f3 * f3;
        }
        if (z < 2) {
            ss0 += __shfl_xor_sync(0xffffffffu, ss0, 1);
            ss0 += __shfl_xor_sync(0xffffffffu, ss0, 2);
            ss1 += __shfl_xor_sync(0xffffffffu, ss1, 1);
            ss1 += __shfl_xor_sync(0xffffffffu, ss1, 2);
            if ((lane & 3) == 0) {
                float* ndst = (z == 0) ? g_Qn : g_Kn;
                ndst[hh * (BDIM * LSEQ) + r0] = ss0;
                ndst[hh * (BDIM * LSEQ) + r1] = ss1;
            }
        }
    }
}

// ---------------- kernel 2: fp16 tensor-core attention, kv-split x2 -------
// (verbatim from passing R16, deg-4 poly via shared helper)
#define AT_SMEM_HALVES 16384
#define AT_SMEM_BYTES (AT_SMEM_HALVES * 2 + 512 + 256)   // 33536

__global__ __launch_bounds__(128)
void attn_mma(float* __restrict__ score_out) {
    extern __shared__ __half smh[];
    float* kn = (float*)(smh + AT_SMEM_HALVES);
    const int tid = threadIdx.x, lane = tid & 31, wid = tid >> 5;
    const int q0 = blockIdx.x * 64;
    const int hb = blockIdx.y, h = hb >> 2, b = hb & 3;
    const int z = blockIdx.z;
    const size_t XSZ = (size_t)BDIM * LSEQ * UDIM;
    const __half* Qf_g = g_Pf;
    const __half* Kf_g = g_Pf + XSZ;
    const __half* Vf_g = g_Pf + 2 * XSZ;

    auto load_tile = [&](const __half* src, int row0, int dstoff) {
        #pragma unroll
        for (int i = 0; i < 4; i++) {
            int qid = tid + i * 128;
            int r = qid >> 3, c = qid & 7;
            cpa16(smh + dstoff + r * 64 + ((c ^ (r & 7)) << 3),
                  src + (size_t)(b * LSEQ + row0 + r) * UDIM + h * DDIM + c * 8);
        }
    };
    auto issue_K = [&](int tl) {
        int row0 = (z * 4 + tl) * 64;
        load_tile(Kf_g, row0, 4096 + (tl & 1) * 4096);
        if (tid < 16) cpa16(kn + (tl & 1) * 64 + tid * 4,
                            g_Kn + (size_t)h * (BDIM * LSEQ) + b * LSEQ + row0 + tid * 4);
    };
    auto issue_V = [&](int tl) {
        int row0 = (z * 4 + tl) * 64;
        load_tile(Vf_g, row0, 12288);
    };

    load_tile(Qf_g, q0, 0);
    issue_K(0);
    CPA_COMMIT();

    const int rr = lane >> 2;
    const int qrow = q0 + wid * 16 + rr;
    float qq0 = g_Qn[(size_t)h * (BDIM * LSEQ) + b * LSEQ + qrow];
    float qq1 = g_Qn[(size_t)h * (BDIM * LSEQ) + b * LSEQ + qrow + 8];
    float qm0 = g_qm[b * LSEQ + qrow];
    float qm1 = g_qm[b * LSEQ + qrow + 8];

    const uint32_t smem_u = (uint32_t)__cvta_generic_to_shared(smh);
    const int arow = wid * 16 + (lane & 15);
    const int asel = lane >> 4;
    const int nrow = (lane & 7) + ((lane >> 4) << 3);
    const int nhalf = (lane >> 3) & 1;
    const int vkrow = (lane & 7) + (((lane >> 3) & 1) << 3);
    const int vdsel = lane >> 4;

    uint32_t qf[4][4];
    float o[8][4];
    #pragma unroll
    for (int nf = 0; nf < 8; nf++)
        #pragma unroll
        for (int e = 0; e < 4; e++) o[nf][e] = 0.f;
    float l0 = 0.f, l1 = 0.f;
    const float C8 = 0.18033688f;    // log2(e)/8

    for (int t = 0; t < 4; t++) {
        issue_V(t);
        CPA_COMMIT();
        if (t < 3) issue_K(t + 1);
        CPA_COMMIT();
        CPA_WAIT(2);
        __syncthreads();

        if (t == 0) {
            #pragma unroll
            for (int ks = 0; ks < 4; ks++) {
                uint32_t aoff = (uint32_t)(arow * 64 + (((ks * 2 + asel) ^ (lane & 7)) << 3)) * 2;
                ldsm4(qf[ks], smem_u + aoff);
            }
        }

        const uint32_t kb = smem_u + (4096 + (t & 1) * 4096) * 2;

        float s[8][4];
        #pragma unroll
        for (int nf = 0; nf < 8; nf++)
            #pragma unroll
            for (int e = 0; e < 4; e++) s[nf][e] = 0.f;
        #pragma unroll
        for (int ks = 0; ks < 4; ks++) {
            uint32_t kh[4][4];
            #pragma unroll
            for (int g = 0; g < 4; g++) {
                uint32_t off = (uint32_t)((g * 16 + nrow) * 64 +
                                          (((ks * 2 + nhalf) ^ (lane & 7)) << 3)) * 2;
                ldsm4(kh[g], kb + off);
            }
            #pragma unroll
            for (int nf = 0; nf < 8; nf++)
                mma_f16(s[nf], qf[ks], &kh[nf >> 1][(nf & 1) * 2]);
        }

        uint32_t pa[8][2];
        #pragma unroll
        for (int nf = 0; nf < 8; nf++) {
            int c0 = nf * 8 + (lane & 3) * 2;
            float kk0 = kn[(t & 1) * 64 + c0];
            float kk1 = kn[(t & 1) * 64 + c0 + 1];
            float e0 = fmaxf(qq0 + kk0 - 2.f * s[nf][0], 1e-12f);
            float e1 = fmaxf(qq0 + kk1 - 2.f * s[nf][1], 1e-12f);
            float e2 = fmaxf(qq1 + kk0 - 2.f * s[nf][2], 1e-12f);
            float e3 = fmaxf(qq1 + kk1 - 2.f * s[nf][3], 1e-12f);
            float sq0 = sqrt_nm(e0), sq1 = sqrt_nm(e1);
            float sq2 = sqrt_nm(e2), sq3 = sqrt_nm(e3);
            size_t sr0 = ((size_t)(hb * LSEQ + qrow)) * LSEQ + (z * 4 + t) * 64 + c0;
            size_t sr1 = sr0 + (size_t)8 * LSEQ;
            *(float2*)(score_out + sr0) = make_float2(-0.125f * sq0 * qm0, -0.125f * sq1 * qm0);
            *(float2*)(score_out + sr1) = make_float2(-0.125f * sq2 * qm1, -0.125f * sq3 * qm1);
            float p0 = exp2_poly(-C8 * sq0);
            float p1 = exp2_poly(-C8 * sq1);
            float p2 = exp2_poly(-C8 * sq2);
            float p3 = exp2_poly(-C8 * sq3);
            l0 += p0 + p1; l1 += p2 + p3;
            pa[nf][0] = packh2(p0, p1);
            pa[nf][1] = packh2(p2, p3);
        }

        CPA_WAIT(1);
        __syncthreads();

        const uint32_t vb = smem_u + 12288 * 2;
        #pragma unroll
        for (int ks = 0; ks < 4; ks++) {
            uint32_t vh[4][4];
            #pragma unroll
            for (int g = 0; g < 4; g++) {
                int row = ks * 16 + vkrow;
                uint32_t off = (uint32_t)(row * 64 + (((g * 2 + vdsel) ^ (lane & 7)) << 3)) * 2;
                ldsm4t(vh[g], vb + off);
            }
            uint32_t Ah[4] = {pa[2 * ks][0], pa[2 * ks][1], pa[2 * ks + 1][0], pa[2 * ks + 1][1]};
            #pragma unroll
            for (int nf = 0; nf < 8; nf++)
                mma_f16(o[nf], Ah, &vh[nf >> 1][(nf & 1) * 2]);
        }
        __syncthreads();
    }

    l0 += __shfl_xor_sync(0xffffffffu, l0, 1);
    l0 += __shfl_xor_sync(0xffffffffu, l0, 2);
    l1 += __shfl_xor_sync(0xffffffffu, l1, 1);
    l1 += __shfl_xor_sync(0xffffffffu, l1, 2);

    size_t prow = (size_t)(z * HBDIM + hb) * LSEQ + qrow;
    #pragma unroll
    for (int nf = 0; nf < 8; nf++) {
        int col = nf * 8 + (lane & 3) * 2;
        *(float2*)(g_Opart + prow * DDIM + col) = make_float2(o[nf][0], o[nf][1]);
        *(float2*)(g_Opart + (prow + 8) * DDIM + col) = make_float2(o[nf][2], o[nf][3]);
    }
    if ((lane & 3) == 0) {
        g_lpart[prow] = l0;
        g_lpart[prow + 8] = l1;
    }
}

// ---------------- kernel 3: combine kv-split halves ----------------
__global__ void combine_kernel(float* __restrict__ out) {
    int g = blockIdx.x * 256 + threadIdx.x;
    int d = (g & 31) * 2;
    int row = g >> 5;                                 // hb*LSEQ + q
    float2 a = *(float2*)(g_Opart + (size_t)row * DDIM + d);
    float2 c = *(float2*)(g_Opart + ((size_t)(HBDIM * LSEQ) + row) * DDIM + d);
    float l = g_lpart[row] + g_lpart[HBDIM * LSEQ + row];
    int hb = row >> 9, q = row & 511;
    int h = hb >> 2, b = hb & 3;
    float s = g_qm[b * LSEQ + q] / l;
    *(float2*)(out + ((size_t)(b * LSEQ + q)) * UDIM + h * DDIM + d) =
        make_float2((a.x + c.x) * s, (a.y + c.y) * s);
}

// ---------------- launcher ----------------
extern "C" void kernel_launch(void* const* d_in, const int* in_sizes, int n_in,
                              void* d_out, int out_size) {
    (void)in_sizes; (void)n_in; (void)out_size;
    const float* queries = (const float*)d_in[0];
    const float* keys    = (const float*)d_in[1];
    const float* values  = (const float*)d_in[2];
    const float* Wq = (const float*)d_in[3];
    const float* bq = (const float*)d_in[4];
    const float* Wk = (const float*)d_in[5];
    const float* bk = (const float*)d_in[6];
    const float* Wv = (const float*)d_in[7];
    const float* bv = (const float*)d_in[8];

    float* out_ptr   = (float*)d_out;
    float* score_ptr = out_ptr + (size_t)BDIM * LSEQ * UDIM;

    cudaFuncSetAttribute(qkv_gemm_f16, cudaFuncAttributeMaxDynamicSharedMemorySize,
                         GEMM_SMEM_BYTES);
    cudaFuncSetAttribute(attn_mma, cudaFuncAttributeMaxDynamicSharedMemorySize,
                         AT_SMEM_BYTES);

    dim3 pxgrid((BDIM * LSEQ * UDIM) / (256 * 4), 3);
    prep_x_kernel<<<pxgrid, 256>>>(queries, keys, values);

    dim3 twgrid(UDIM / 32, UDIM / 32, 3);
    transpose_w_kernel<<<twgrid, 256>>>(Wq, Wk, Wv);

    dim3 ggrid(BDIM * LSEQ / 128, UDIM / 64, 3);
    qkv_gemm_f16<<<ggrid, 256, GEMM_SMEM_BYTES>>>(bq, bk, bv);

    dim3 agrid(LSEQ / 64, HBDIM, 2);
    attn_mma<<<agrid, 128, AT_SMEM_BYTES>>>(score_ptr);

    combine_kernel<<<(HBDIM * LSEQ * DDIM / 2) / 256, 256>>>(out_ptr);
}